// round 3
// baseline (speedup 1.0000x reference)
#include <cuda_runtime.h>
#include <cuda_bf16.h>
#include <cstdint>

// GNN_84421877170708: 4-layer GCL GNN.
// Edge MLP on mma.sync tf32 (sm_80-class PTX; tcgen05 unavailable: harness
// targets plain sm_103). Node path stays fp32 with packed fma.rn.f32x2.

#define N_NODES 50000
#define E_EDGES 800000
#define IN_NF   64
#define HID     128
#define EH      64
#define OUT_NF  64
#define L_LAYERS 4
#define TILE    128           // edges per CTA tile

__device__ float g_h[N_NODES * HID];
__device__ float g_agg[N_NODES * EH];
__device__ float g_z[N_NODES * HID];

using u64 = unsigned long long;
using u32 = unsigned int;

__device__ __forceinline__ float silu(float v) {
    return __fdividef(v, 1.0f + __expf(-v));
}
__device__ __forceinline__ u32 f2tf32(float f) {
    u32 r; asm("cvt.rna.tf32.f32 %0, %1;" : "=r"(r) : "f"(f)); return r;
}
__device__ __forceinline__ float tf32f(float f) {   // value with tf32 bit pattern
    return __uint_as_float(f2tf32(f));
}
__device__ __forceinline__ void mma_tf32(float* c, u32 a0, u32 a1, u32 a2, u32 a3,
                                         u32 b0, u32 b1) {
    asm volatile(
        "mma.sync.aligned.m16n8k8.row.col.f32.tf32.tf32.f32 "
        "{%0,%1,%2,%3}, {%4,%5,%6,%7}, {%8,%9}, {%0,%1,%2,%3};"
        : "+f"(c[0]), "+f"(c[1]), "+f"(c[2]), "+f"(c[3])
        : "r"(a0), "r"(a1), "r"(a2), "r"(a3), "r"(b0), "r"(b1));
}
__device__ __forceinline__ void red2(float* p, float v0, float v1) {
    asm volatile("red.global.add.v2.f32 [%0], {%1,%2};" :: "l"(p), "f"(v0), "f"(v1) : "memory");
}

// fragment-interleave word offset within a row: k -> (k>>3)*8 + (k&3)*2 + ((k>>2)&1)
__device__ __forceinline__ int woff(int k) {
    return (k >> 3) * 8 + (k & 3) * 2 + ((k >> 2) & 1);
}

// SMEM layout (floats)
#define SM_IDX   0            // 128 ints
#define SM_B1S   128          // 64
#define SM_B2S   192          // 64
#define SM_X     256          // 128 x 140
#define SM_X2    18176        // 128 x 76
#define SM_B1P   27904        // 32 s x 4 jp x 32 lane x 4
#define SM_B2P   44288        // 8  s x 4 jp x 32 lane x 4
#define SM_EDGE_FLOATS 48384
#define SM_EDGE_BYTES  (SM_EDGE_FLOATS * 4)

// ---------------------------------------------------------------------------
// Edge kernel: per 128-edge tile
//   MMA1: D1[128x64] = [tf32(h[row]) | tf32(h[col])] @ W1   (K=256)
//   X2   = tf32(silu(D1 + b1))
//   MMA2: D2[128x64] = X2 @ W2                               (K=64)
//   red.global.add.v2 silu(D2 + b2) into g_agg[row]
// 16 warps: warp -> (mg = warp>>1: rows mg*16..+15, ng = warp&1: cols ng*32..+31)
// ---------------------------------------------------------------------------
__global__ void __launch_bounds__(512, 1)
edge_mma_kernel(const int* __restrict__ edges,
                const float* __restrict__ W1, const float* __restrict__ b1,
                const float* __restrict__ W2, const float* __restrict__ b2)
{
    extern __shared__ float sm[];
    int*   idxs = (int*)sm;
    float* b1s  = sm + SM_B1S;
    float* b2s  = sm + SM_B2S;
    float* X    = sm + SM_X;
    float* X2   = sm + SM_X2;
    float* B1p  = sm + SM_B1P;
    float* B2p  = sm + SM_B2P;

    const int tid  = threadIdx.x;
    const int warp = tid >> 5, lane = tid & 31;
    const int g    = lane >> 2, tig = lane & 3;
    const int mg   = warp >> 1, ng  = warp & 1;

    // ---- prepack W1 into per-lane fragment order (tf32) ----
    for (int i = tid; i < 32 * 4 * 32; i += 512) {
        int s  = i >> 7;          // k-step 0..31
        int jp = (i >> 5) & 3;    // n-tile pair 0..3
        int ln = i & 31;
        int gg = ln >> 2, tt = ln & 3;
        int k0 = s * 8, n0 = jp * 16;
        float4 v;
        v.x = tf32f(W1[(k0 + tt)     * 64 + n0 + gg]);
        v.y = tf32f(W1[(k0 + tt + 4) * 64 + n0 + gg]);
        v.z = tf32f(W1[(k0 + tt)     * 64 + n0 + 8 + gg]);
        v.w = tf32f(W1[(k0 + tt + 4) * 64 + n0 + 8 + gg]);
        *(float4*)&B1p[i * 4] = v;
    }
    for (int i = tid; i < 8 * 4 * 32; i += 512) {
        int s  = i >> 7;
        int jp = (i >> 5) & 3;
        int ln = i & 31;
        int gg = ln >> 2, tt = ln & 3;
        int k0 = s * 8, n0 = jp * 16;
        float4 v;
        v.x = tf32f(W2[(k0 + tt)     * 64 + n0 + gg]);
        v.y = tf32f(W2[(k0 + tt + 4) * 64 + n0 + gg]);
        v.z = tf32f(W2[(k0 + tt)     * 64 + n0 + 8 + gg]);
        v.w = tf32f(W2[(k0 + tt + 4) * 64 + n0 + 8 + gg]);
        *(float4*)&B2p[i * 4] = v;
    }
    if (tid < 64) { b1s[tid] = b1[tid]; b2s[tid] = b2[tid]; }
    __syncthreads();

    const int r_lo = mg * 16 + g;           // output row (low half)
    const float* xlo = X  + r_lo * 140 + tig * 2;
    const float* xhi = xlo + 8 * 140;
    const float* ylo = X2 + r_lo * 76 + tig * 2;
    const float* yhi = ylo + 8 * 76;

    for (int t = blockIdx.x; t < E_EDGES / TILE; t += gridDim.x) {
        float acc[4][4];
#pragma unroll
        for (int a = 0; a < 4; a++)
#pragma unroll
            for (int c = 0; c < 4; c++) acc[a][c] = 0.f;

        // ======== MLP1: two phases (row endpoint, col endpoint) ========
#pragma unroll 1
        for (int ph = 0; ph < 2; ph++) {
            {   // gather: 4 threads per edge-row, 32 features each
                int r = tid >> 2, part = tid & 3;
                int node = edges[ph * E_EDGES + t * TILE + r];
                if (ph == 0 && part == 0) idxs[r] = node;
                const float4* src = (const float4*)(g_h + (size_t)node * HID + part * 32);
                float* xr = X + r * 140;
#pragma unroll
                for (int i = 0; i < 8; i++) {
                    float4 v = src[i];
                    int k = part * 32 + i * 4;
                    int base = (k >> 3) * 8 + ((k >> 2) & 1);
                    xr[base + 0] = tf32f(v.x);
                    xr[base + 2] = tf32f(v.y);
                    xr[base + 4] = tf32f(v.z);
                    xr[base + 6] = tf32f(v.w);
                }
            }
            __syncthreads();

#pragma unroll 4
            for (int s = 0; s < 16; s++) {
                float2 alo = *(const float2*)(xlo + s * 8);
                float2 ahi = *(const float2*)(xhi + s * 8);
                u32 a0 = __float_as_uint(alo.x), a1 = __float_as_uint(ahi.x);
                u32 a2 = __float_as_uint(alo.y), a3 = __float_as_uint(ahi.y);
                int sg = ph * 16 + s;
#pragma unroll
                for (int jp2 = 0; jp2 < 2; jp2++) {
                    int jp = ng * 2 + jp2;
                    float4 bv = *(const float4*)&B1p[((sg * 4 + jp) * 32 + lane) * 4];
                    mma_tf32(acc[jp2 * 2 + 0], a0, a1, a2, a3,
                             __float_as_uint(bv.x), __float_as_uint(bv.y));
                    mma_tf32(acc[jp2 * 2 + 1], a0, a1, a2, a3,
                             __float_as_uint(bv.z), __float_as_uint(bv.w));
                }
            }
            __syncthreads();   // all MMA1 reads of X done before next gather/epilogue
        }

        // ======== epilogue1: X2 = tf32(silu(D1 + b1)) ========
#pragma unroll
        for (int jj = 0; jj < 4; jj++) {
            int col0 = ng * 32 + jj * 8 + tig * 2;
            int col1 = col0 + 1;
            X2[r_lo * 76 + woff(col0)]       = tf32f(silu(acc[jj][0] + b1s[col0]));
            X2[r_lo * 76 + woff(col1)]       = tf32f(silu(acc[jj][1] + b1s[col1]));
            X2[(r_lo + 8) * 76 + woff(col0)] = tf32f(silu(acc[jj][2] + b1s[col0]));
            X2[(r_lo + 8) * 76 + woff(col1)] = tf32f(silu(acc[jj][3] + b1s[col1]));
        }
        __syncthreads();

        // ======== MLP2: K=64 ========
#pragma unroll
        for (int a = 0; a < 4; a++)
#pragma unroll
            for (int c = 0; c < 4; c++) acc[a][c] = 0.f;

#pragma unroll
        for (int s = 0; s < 8; s++) {
            float2 alo = *(const float2*)(ylo + s * 8);
            float2 ahi = *(const float2*)(yhi + s * 8);
            u32 a0 = __float_as_uint(alo.x), a1 = __float_as_uint(ahi.x);
            u32 a2 = __float_as_uint(alo.y), a3 = __float_as_uint(ahi.y);
#pragma unroll
            for (int jp2 = 0; jp2 < 2; jp2++) {
                int jp = ng * 2 + jp2;
                float4 bv = *(const float4*)&B2p[((s * 4 + jp) * 32 + lane) * 4];
                mma_tf32(acc[jp2 * 2 + 0], a0, a1, a2, a3,
                         __float_as_uint(bv.x), __float_as_uint(bv.y));
                mma_tf32(acc[jp2 * 2 + 1], a0, a1, a2, a3,
                         __float_as_uint(bv.z), __float_as_uint(bv.w));
            }
        }

        // ======== epilogue2: scatter silu(D2 + b2) into g_agg[row] ========
        {
            int n_lo = idxs[r_lo];
            int n_hi = idxs[r_lo + 8];
#pragma unroll
            for (int jj = 0; jj < 4; jj++) {
                int col0 = ng * 32 + jj * 8 + tig * 2;
                float v0 = silu(acc[jj][0] + b2s[col0]);
                float v1 = silu(acc[jj][1] + b2s[col0 + 1]);
                red2(g_agg + (size_t)n_lo * EH + col0, v0, v1);
                float v2 = silu(acc[jj][2] + b2s[col0]);
                float v3 = silu(acc[jj][3] + b2s[col0 + 1]);
                red2(g_agg + (size_t)n_hi * EH + col0, v2, v3);
            }
        }
        __syncthreads();   // idxs / X2 protected before next tile
    }
}

// ---------------------------------------------------------------------------
// fp32 node path (unchanged from passing round 1)
// ---------------------------------------------------------------------------
__device__ __forceinline__ void ffma2(u64& acc, u64 x, u64 w) {
    asm("fma.rn.f32x2 %0, %1, %2, %0;" : "+l"(acc) : "l"(x), "l"(w));
}
__device__ __forceinline__ u64 pack2(float x) {
    u64 r; asm("mov.b64 %0, {%1, %1};" : "=l"(r) : "f"(x)); return r;
}
__device__ __forceinline__ u64 packf2(float a, float b) {
    u64 r; asm("mov.b64 %0, {%1, %2};" : "=l"(r) : "f"(a), "f"(b)); return r;
}
__device__ __forceinline__ float2 unpack2(u64 v) {
    float2 r; asm("mov.b64 {%0, %1}, %2;" : "=f"(r.x), "=f"(r.y) : "l"(v)); return r;
}
__device__ __forceinline__ void load_smem(float* dst, const float* __restrict__ src,
                                          int n, int tid, int nthreads) {
    for (int i = tid * 4; i < n; i += nthreads * 4)
        *(float4*)(dst + i) = *(const float4*)(src + i);
}

template<int W1IN, int W2IN, int NOUT, bool DO_SILU, bool DO_RES>
__global__ void __launch_bounds__(256) node_gemm(
    const float* __restrict__ in1, const float* __restrict__ in2,
    const float* __restrict__ W, const float* __restrict__ b,
    float* __restrict__ out)
{
    constexpr int KDIM = W1IN + W2IN;
    constexpr int NR   = NOUT / 8;
    extern __shared__ float fsmem[];
    float* ws = fsmem;
    float* bs = ws + KDIM * NOUT;
    float* warpmem = bs + NOUT;

    const int tid  = threadIdx.x;
    const int warp = tid >> 5;
    const int lane = tid & 31;

    load_smem(ws, W, KDIM * NOUT, tid, 256);
    if (tid < NOUT) bs[tid] = b[tid];
    __syncthreads();

    float* xs = warpmem + warp * (KDIM * 16);
    const int p    = lane >> 2;
    const int q    = lane & 3;
    const int m    = lane >> 1;
    const int half = lane & 1;

    u64 biasr[NR / 2];
#pragma unroll
    for (int g = 0; g < NR / 2; g++)
        biasr[g] = packf2(bs[p * NR + 2 * g], bs[p * NR + 2 * g + 1]);

    const int gw     = blockIdx.x * 8 + warp;
    const int nwarps = gridDim.x * 8;
    const int ntiles = N_NODES / 16;

    for (int t = gw; t < ntiles; t += nwarps) {
        __syncwarp();
        int node = t * 16 + m;
        const float* s1 = in1 + (long long)node * W1IN;
        const float* s2 = (W2IN > 0) ? in2 + (long long)node * W2IN : nullptr;
#pragma unroll
        for (int i = 0; i < KDIM / 8; i++) {
            int kk = half * (KDIM / 2) + i * 4;
            float4 v;
            if (W2IN == 0 || kk < W1IN) v = *(const float4*)(s1 + kk);
            else                        v = *(const float4*)(s2 + (kk - W1IN));
            xs[(kk + 0) * 16 + m] = v.x;
            xs[(kk + 1) * 16 + m] = v.y;
            xs[(kk + 2) * 16 + m] = v.z;
            xs[(kk + 3) * 16 + m] = v.w;
        }
        __syncwarp();

        u64 acc[4][NR / 2];
#pragma unroll
        for (int d = 0; d < 4; d++)
#pragma unroll
            for (int g = 0; g < NR / 2; g++) acc[d][g] = biasr[g];

#pragma unroll 2
        for (int k = 0; k < KDIM; k++) {
            float4 xv = *(const float4*)&xs[k * 16 + q * 4];
            u64 xp[4] = {pack2(xv.x), pack2(xv.y), pack2(xv.z), pack2(xv.w)};
#pragma unroll
            for (int g = 0; g < NR / 4; g++) {
                ulonglong2 wv = *(const ulonglong2*)(ws + k * NOUT + p * NR + g * 4);
#pragma unroll
                for (int d = 0; d < 4; d++) {
                    ffma2(acc[d][2 * g],     xp[d], wv.x);
                    ffma2(acc[d][2 * g + 1], xp[d], wv.y);
                }
            }
        }

#pragma unroll
        for (int d = 0; d < 4; d++) {
            int nn = t * 16 + q * 4 + d;
            float* dst = out + (long long)nn * NOUT + p * NR;
#pragma unroll
            for (int g = 0; g < NR / 4; g++) {
                float2 a = unpack2(acc[d][2 * g]);
                float2 c = unpack2(acc[d][2 * g + 1]);
                float4 v = make_float4(a.x, a.y, c.x, c.y);
                if (DO_SILU) {
                    v.x = silu(v.x); v.y = silu(v.y);
                    v.z = silu(v.z); v.w = silu(v.w);
                }
                if (DO_RES) {
                    float4 r = *(const float4*)(dst + g * 4);
                    v.x += r.x; v.y += r.y; v.z += r.z; v.w += r.w;
                }
                *(float4*)(dst + g * 4) = v;
            }
        }
    }
}

__global__ void zero_agg_kernel() {
    int i = blockIdx.x * blockDim.x + threadIdx.x;
    if (i < N_NODES * EH / 4)
        ((float4*)g_agg)[i] = make_float4(0.f, 0.f, 0.f, 0.f);
}

// ---------------------------------------------------------------------------
extern "C" void kernel_launch(void* const* d_in, const int* in_sizes, int n_in,
                              void* d_out, int out_size)
{
    const float* h_in  = (const float*)d_in[0];
    const int*   edges = (const int*)d_in[1];
    const float* W_in  = (const float*)d_in[2];
    const float* b_in  = (const float*)d_in[3];
    const float* eW1   = (const float*)d_in[4];
    const float* eb1   = (const float*)d_in[5];
    const float* eW2   = (const float*)d_in[6];
    const float* eb2   = (const float*)d_in[7];
    const float* nW1   = (const float*)d_in[8];
    const float* nb1   = (const float*)d_in[9];
    const float* nW2   = (const float*)d_in[10];
    const float* nb2   = (const float*)d_in[11];
    const float* W_out = (const float*)d_in[12];
    const float* b_out = (const float*)d_in[13];

    float* ph;  cudaGetSymbolAddress((void**)&ph,  g_h);
    float* pag; cudaGetSymbolAddress((void**)&pag, g_agg);
    float* pz;  cudaGetSymbolAddress((void**)&pz,  g_z);

    const int smem_na = ((192 * 128 + 128) + 8 * (192 * 16)) * 4;
    const int smem_nb = ((128 * 128 + 128) + 8 * (128 * 16)) * 4;
    const int smem_ei = ((64 * 128 + 128) + 8 * (64 * 16)) * 4;
    const int smem_eo = ((128 * 64 + 64) + 8 * (128 * 16)) * 4;

    cudaFuncSetAttribute(edge_mma_kernel, cudaFuncAttributeMaxDynamicSharedMemorySize, SM_EDGE_BYTES);
    cudaFuncSetAttribute(node_gemm<64, 0, 128, false, false>,
                         cudaFuncAttributeMaxDynamicSharedMemorySize, smem_ei);
    cudaFuncSetAttribute(node_gemm<128, 64, 128, true, false>,
                         cudaFuncAttributeMaxDynamicSharedMemorySize, smem_na);
    cudaFuncSetAttribute(node_gemm<128, 0, 128, false, true>,
                         cudaFuncAttributeMaxDynamicSharedMemorySize, smem_nb);
    cudaFuncSetAttribute(node_gemm<128, 0, 64, false, false>,
                         cudaFuncAttributeMaxDynamicSharedMemorySize, smem_eo);

    node_gemm<64, 0, 128, false, false><<<148, 256, smem_ei>>>(
        h_in, nullptr, W_in, b_in, ph);

    for (int l = 0; l < L_LAYERS; l++) {
        zero_agg_kernel<<<(N_NODES * EH / 4 + 255) / 256, 256>>>();
        edge_mma_kernel<<<148, 512, SM_EDGE_BYTES>>>(
            edges, eW1 + l * 2 * HID * EH, eb1 + l * EH,
            eW2 + l * EH * EH, eb2 + l * EH);
        node_gemm<128, 64, 128, true, false><<<148, 256, smem_na>>>(
            ph, pag, nW1 + l * (HID + EH) * HID, nb1 + l * HID, pz);
        node_gemm<128, 0, 128, false, true><<<148, 256, smem_nb>>>(
            pz, nullptr, nW2 + l * HID * HID, nb2 + l * HID, ph);
    }

    node_gemm<128, 0, 64, false, false><<<148, 256, smem_eo>>>(
        ph, nullptr, W_out, b_out, (float*)d_out);
}

// round 4
// speedup vs baseline: 3.0185x; 3.0185x over previous
#include <cuda_runtime.h>
#include <cuda_bf16.h>
#include <cstdint>

// GNN_84421877170708: 4-layer GCL GNN.
// Key restructure: edge-MLP layer-1 is linear per endpoint ->
//   P = h @ [W1a|W1b] precomputed per NODE (dense fp32 GEMM),
//   edge kernel = gather-add + silu + small tf32 mma MLP2 + scatter.

#define N_NODES 50000
#define E_EDGES 800000
#define IN_NF   64
#define HID     128
#define EH      64
#define OUT_NF  64
#define L_LAYERS 4
#define ET      128            // edges per tile in edge kernel

__device__ float g_h[N_NODES * HID];
__device__ float g_agg[N_NODES * EH];
__device__ float g_z[N_NODES * HID];    // doubles as P buffer per layer
__device__ float g_wcat[HID * HID];     // repacked [W1a|W1b]  [128 x 128]
__device__ float g_bcat[HID];           // [b1 | 0]

using u64 = unsigned long long;
using u32 = unsigned int;

__device__ __forceinline__ float silu(float v) {
    float h = 0.5f * v, t;
    asm("tanh.approx.f32 %0, %1;" : "=f"(t) : "f"(h));
    return fmaf(h, t, h);
}
__device__ __forceinline__ u32 f2tf32(float f) {
    u32 r; asm("cvt.rna.tf32.f32 %0, %1;" : "=r"(r) : "f"(f)); return r;
}
__device__ __forceinline__ float tf32f(float f) {
    return __uint_as_float(f2tf32(f));
}
__device__ __forceinline__ void mma_tf32(float* c, u32 a0, u32 a1, u32 a2, u32 a3,
                                         u32 b0, u32 b1) {
    asm volatile(
        "mma.sync.aligned.m16n8k8.row.col.f32.tf32.tf32.f32 "
        "{%0,%1,%2,%3}, {%4,%5,%6,%7}, {%8,%9}, {%0,%1,%2,%3};"
        : "+f"(c[0]), "+f"(c[1]), "+f"(c[2]), "+f"(c[3])
        : "r"(a0), "r"(a1), "r"(a2), "r"(a3), "r"(b0), "r"(b1));
}
__device__ __forceinline__ void red2(float* p, float v0, float v1) {
    asm volatile("red.global.add.v2.f32 [%0], {%1,%2};" :: "l"(p), "f"(v0), "f"(v1) : "memory");
}

// ---------------------------------------------------------------------------
// Repack W1 [256 x 64] -> Wcat [128 x 128] with Wcat[k][j<64] = W1a[k][j],
// Wcat[k][j>=64] = W1b[k][j-64]; bcat = [b1 | 0].
// ---------------------------------------------------------------------------
__global__ void repack_w1(const float* __restrict__ eW1, const float* __restrict__ b1) {
    int i = blockIdx.x * 256 + threadIdx.x;
    if (i < HID * HID) {
        int k = i >> 7, j = i & 127;
        g_wcat[i] = (j < 64) ? eW1[k * 64 + j] : eW1[(k + 128) * 64 + (j - 64)];
    }
    if (i < HID) g_bcat[i] = (i < 64) ? b1[i] : 0.f;
}

// ---------------------------------------------------------------------------
// Edge kernel: per 128-edge tile (256 threads, 8 warps, 3 CTAs/SM)
//   X2[e][:] = tf32(silu(P[row][0:64] + P[col][64:128]))      (gather phase)
//   D2[128x64] = X2 @ W2  via mma.sync tf32 (K=64)
//   red.global.add.v2 silu(D2 + b2) into g_agg[row]
// SMEM floats: idx[128] | b2s[64] | X2[128*66] | B2p[8*4*32*4]
// ---------------------------------------------------------------------------
#define SM_IDX  0
#define SM_B2S  128
#define SM_X2   192
#define SM_B2P  (192 + 128 * 66)
#define SM_EDGE_FLOATS (SM_B2P + 8 * 4 * 32 * 4)
#define SM_EDGE_BYTES  (SM_EDGE_FLOATS * 4)

__global__ void __launch_bounds__(256, 3)
edge_kernel2(const int* __restrict__ edges, const float* __restrict__ P,
             const float* __restrict__ W2, const float* __restrict__ b2)
{
    extern __shared__ float sm[];
    int*   idxs = (int*)sm;
    float* b2s  = sm + SM_B2S;
    float* X2   = sm + SM_X2;
    float* B2p  = sm + SM_B2P;

    const int tid  = threadIdx.x;
    const int warp = tid >> 5, lane = tid & 31;
    const int g    = lane >> 2, tig = lane & 3;

    // prepack W2 into per-lane fragment order (tf32)
    for (int i = tid; i < 8 * 4 * 32; i += 256) {
        int s  = i >> 7;
        int jp = (i >> 5) & 3;
        int ln = i & 31;
        int gg = ln >> 2, tt = ln & 3;
        int k0 = s * 8, n0 = jp * 16;
        float4 v;
        v.x = tf32f(W2[(k0 + tt)     * 64 + n0 + gg]);
        v.y = tf32f(W2[(k0 + tt + 4) * 64 + n0 + gg]);
        v.z = tf32f(W2[(k0 + tt)     * 64 + n0 + 8 + gg]);
        v.w = tf32f(W2[(k0 + tt + 4) * 64 + n0 + 8 + gg]);
        *(float4*)&B2p[i * 4] = v;
    }
    if (tid < 64) b2s[tid] = b2[tid];
    __syncthreads();

    const float* xlo = X2 + (warp * 16 + g) * 66 + tig * 2;
    const float* xhi = xlo + 8 * 66;

    for (int t = blockIdx.x; t < E_EDGES / ET; t += gridDim.x) {
        // ---- gather + silu -> X2 (frag-interleaved tf32) ----
        {
            int e = tid >> 1, half = tid & 1;
            int row  = edges[t * ET + e];
            int coln = edges[E_EDGES + t * ET + e];
            if (half == 0) idxs[e] = row;
            const float4* pa = (const float4*)(P + (size_t)row  * HID + half * 32);
            const float4* pb = (const float4*)(P + (size_t)coln * HID + 64 + half * 32);
            float va[32];
#pragma unroll
            for (int i = 0; i < 8; i++) {
                float4 x = pa[i];
                float4 y = pb[i];
                va[i * 4 + 0] = tf32f(silu(x.x + y.x));
                va[i * 4 + 1] = tf32f(silu(x.y + y.y));
                va[i * 4 + 2] = tf32f(silu(x.z + y.z));
                va[i * 4 + 3] = tf32f(silu(x.w + y.w));
            }
            float* xr = X2 + e * 66;
#pragma unroll
            for (int b = 0; b < 4; b++)
#pragma unroll
                for (int j = 0; j < 4; j++) {
                    float2 v = make_float2(va[(b * 2) * 4 + j], va[(b * 2 + 1) * 4 + j]);
                    *(float2*)&xr[(half * 4 + b) * 8 + j * 2] = v;
                }
        }
        __syncthreads();

        // ---- MLP2 MMA: rows warp*16..+15, all 64 cols ----
        float acc[8][4];
#pragma unroll
        for (int a = 0; a < 8; a++)
#pragma unroll
            for (int c = 0; c < 4; c++) acc[a][c] = 0.f;

#pragma unroll
        for (int s = 0; s < 8; s++) {
            float2 alo = *(const float2*)(xlo + s * 8);
            float2 ahi = *(const float2*)(xhi + s * 8);
            u32 a0 = __float_as_uint(alo.x), a1 = __float_as_uint(ahi.x);
            u32 a2 = __float_as_uint(alo.y), a3 = __float_as_uint(ahi.y);
#pragma unroll
            for (int jp = 0; jp < 4; jp++) {
                float4 bv = *(const float4*)&B2p[((s * 4 + jp) * 32 + lane) * 4];
                mma_tf32(acc[jp * 2 + 0], a0, a1, a2, a3,
                         __float_as_uint(bv.x), __float_as_uint(bv.y));
                mma_tf32(acc[jp * 2 + 1], a0, a1, a2, a3,
                         __float_as_uint(bv.z), __float_as_uint(bv.w));
            }
        }

        // ---- epilogue: silu + scatter ----
        {
            int nlo = idxs[warp * 16 + g];
            int nhi = idxs[warp * 16 + g + 8];
            float* dlo = g_agg + (size_t)nlo * EH;
            float* dhi = g_agg + (size_t)nhi * EH;
#pragma unroll
            for (int a = 0; a < 8; a++) {
                int c0 = (a >> 1) * 16 + (a & 1) * 8 + tig * 2;
                red2(dlo + c0, silu(acc[a][0] + b2s[c0]), silu(acc[a][1] + b2s[c0 + 1]));
                red2(dhi + c0, silu(acc[a][2] + b2s[c0]), silu(acc[a][3] + b2s[c0 + 1]));
            }
        }
        __syncthreads();   // X2/idxs protected before next tile
    }
}

// ---------------------------------------------------------------------------
// fp32 node path (proven; f32x2 packed FMA)
// ---------------------------------------------------------------------------
__device__ __forceinline__ void ffma2(u64& acc, u64 x, u64 w) {
    asm("fma.rn.f32x2 %0, %1, %2, %0;" : "+l"(acc) : "l"(x), "l"(w));
}
__device__ __forceinline__ u64 pack2(float x) {
    u64 r; asm("mov.b64 %0, {%1, %1};" : "=l"(r) : "f"(x)); return r;
}
__device__ __forceinline__ u64 packf2(float a, float b) {
    u64 r; asm("mov.b64 %0, {%1, %2};" : "=l"(r) : "f"(a), "f"(b)); return r;
}
__device__ __forceinline__ float2 unpack2(u64 v) {
    float2 r; asm("mov.b64 {%0, %1}, %2;" : "=f"(r.x), "=f"(r.y) : "l"(v)); return r;
}
__device__ __forceinline__ void load_smem(float* dst, const float* __restrict__ src,
                                          int n, int tid, int nthreads) {
    for (int i = tid * 4; i < n; i += nthreads * 4)
        *(float4*)(dst + i) = *(const float4*)(src + i);
}

template<int W1IN, int W2IN, int NOUT, bool DO_SILU, bool DO_RES>
__global__ void __launch_bounds__(256) node_gemm(
    const float* __restrict__ in1, const float* __restrict__ in2,
    const float* __restrict__ W, const float* __restrict__ b,
    float* __restrict__ out)
{
    constexpr int KDIM = W1IN + W2IN;
    constexpr int NR   = NOUT / 8;
    extern __shared__ float fsmem[];
    float* ws = fsmem;
    float* bs = ws + KDIM * NOUT;
    float* warpmem = bs + NOUT;

    const int tid  = threadIdx.x;
    const int warp = tid >> 5;
    const int lane = tid & 31;

    load_smem(ws, W, KDIM * NOUT, tid, 256);
    if (tid < NOUT) bs[tid] = b[tid];
    __syncthreads();

    float* xs = warpmem + warp * (KDIM * 16);
    const int p    = lane >> 2;
    const int q    = lane & 3;
    const int m    = lane >> 1;
    const int half = lane & 1;

    u64 biasr[NR / 2];
#pragma unroll
    for (int g = 0; g < NR / 2; g++)
        biasr[g] = packf2(bs[p * NR + 2 * g], bs[p * NR + 2 * g + 1]);

    const int gw     = blockIdx.x * 8 + warp;
    const int nwarps = gridDim.x * 8;
    const int ntiles = N_NODES / 16;

    for (int t = gw; t < ntiles; t += nwarps) {
        __syncwarp();
        int node = t * 16 + m;
        const float* s1 = in1 + (long long)node * W1IN;
        const float* s2 = (W2IN > 0) ? in2 + (long long)node * W2IN : nullptr;
#pragma unroll
        for (int i = 0; i < KDIM / 8; i++) {
            int kk = half * (KDIM / 2) + i * 4;
            float4 v;
            if (W2IN == 0 || kk < W1IN) v = *(const float4*)(s1 + kk);
            else                        v = *(const float4*)(s2 + (kk - W1IN));
            xs[(kk + 0) * 16 + m] = v.x;
            xs[(kk + 1) * 16 + m] = v.y;
            xs[(kk + 2) * 16 + m] = v.z;
            xs[(kk + 3) * 16 + m] = v.w;
        }
        __syncwarp();

        u64 acc[4][NR / 2];
#pragma unroll
        for (int d = 0; d < 4; d++)
#pragma unroll
            for (int g = 0; g < NR / 2; g++) acc[d][g] = biasr[g];

#pragma unroll 2
        for (int k = 0; k < KDIM; k++) {
            float4 xv = *(const float4*)&xs[k * 16 + q * 4];
            u64 xp[4] = {pack2(xv.x), pack2(xv.y), pack2(xv.z), pack2(xv.w)};
#pragma unroll
            for (int g = 0; g < NR / 4; g++) {
                ulonglong2 wv = *(const ulonglong2*)(ws + k * NOUT + p * NR + g * 4);
#pragma unroll
                for (int d = 0; d < 4; d++) {
                    ffma2(acc[d][2 * g],     xp[d], wv.x);
                    ffma2(acc[d][2 * g + 1], xp[d], wv.y);
                }
            }
        }

#pragma unroll
        for (int d = 0; d < 4; d++) {
            int nn = t * 16 + q * 4 + d;
            float* dst = out + (long long)nn * NOUT + p * NR;
#pragma unroll
            for (int g = 0; g < NR / 4; g++) {
                float2 a = unpack2(acc[d][2 * g]);
                float2 c = unpack2(acc[d][2 * g + 1]);
                float4 v = make_float4(a.x, a.y, c.x, c.y);
                if (DO_SILU) {
                    v.x = silu(v.x); v.y = silu(v.y);
                    v.z = silu(v.z); v.w = silu(v.w);
                }
                if (DO_RES) {
                    float4 r = *(const float4*)(dst + g * 4);
                    v.x += r.x; v.y += r.y; v.z += r.z; v.w += r.w;
                }
                *(float4*)(dst + g * 4) = v;
            }
        }
    }
}

__global__ void zero_agg_kernel() {
    int i = blockIdx.x * blockDim.x + threadIdx.x;
    if (i < N_NODES * EH / 4)
        ((float4*)g_agg)[i] = make_float4(0.f, 0.f, 0.f, 0.f);
}

// ---------------------------------------------------------------------------
extern "C" void kernel_launch(void* const* d_in, const int* in_sizes, int n_in,
                              void* d_out, int out_size)
{
    const float* h_in  = (const float*)d_in[0];
    const int*   edges = (const int*)d_in[1];
    const float* W_in  = (const float*)d_in[2];
    const float* b_in  = (const float*)d_in[3];
    const float* eW1   = (const float*)d_in[4];
    const float* eb1   = (const float*)d_in[5];
    const float* eW2   = (const float*)d_in[6];
    const float* eb2   = (const float*)d_in[7];
    const float* nW1   = (const float*)d_in[8];
    const float* nb1   = (const float*)d_in[9];
    const float* nW2   = (const float*)d_in[10];
    const float* nb2   = (const float*)d_in[11];
    const float* W_out = (const float*)d_in[12];
    const float* b_out = (const float*)d_in[13];

    float* ph;   cudaGetSymbolAddress((void**)&ph,   g_h);
    float* pag;  cudaGetSymbolAddress((void**)&pag,  g_agg);
    float* pz;   cudaGetSymbolAddress((void**)&pz,   g_z);
    float* pwc;  cudaGetSymbolAddress((void**)&pwc,  g_wcat);
    float* pbc;  cudaGetSymbolAddress((void**)&pbc,  g_bcat);

    const int smem_na = ((192 * 128 + 128) + 8 * (192 * 16)) * 4;
    const int smem_nb = ((128 * 128 + 128) + 8 * (128 * 16)) * 4;
    const int smem_ei = ((64 * 128 + 128) + 8 * (64 * 16)) * 4;
    const int smem_eo = ((128 * 64 + 64) + 8 * (128 * 16)) * 4;

    cudaFuncSetAttribute(edge_kernel2, cudaFuncAttributeMaxDynamicSharedMemorySize, SM_EDGE_BYTES);
    cudaFuncSetAttribute(node_gemm<64, 0, 128, false, false>,
                         cudaFuncAttributeMaxDynamicSharedMemorySize, smem_ei);
    cudaFuncSetAttribute(node_gemm<128, 64, 128, true, false>,
                         cudaFuncAttributeMaxDynamicSharedMemorySize, smem_na);
    cudaFuncSetAttribute(node_gemm<128, 0, 128, false, true>,
                         cudaFuncAttributeMaxDynamicSharedMemorySize, smem_nb);
    cudaFuncSetAttribute(node_gemm<128, 0, 128, false, false>,
                         cudaFuncAttributeMaxDynamicSharedMemorySize, smem_nb);
    cudaFuncSetAttribute(node_gemm<128, 0, 64, false, false>,
                         cudaFuncAttributeMaxDynamicSharedMemorySize, smem_eo);

    // embedding_in: g_h = h @ W_in + b_in
    node_gemm<64, 0, 128, false, false><<<148, 256, smem_ei>>>(
        h_in, nullptr, W_in, b_in, ph);

    for (int l = 0; l < L_LAYERS; l++) {
        zero_agg_kernel<<<(N_NODES * EH / 4 + 255) / 256, 256>>>();
        repack_w1<<<64, 256>>>(eW1 + l * 2 * HID * EH, eb1 + l * EH);
        // P = h @ [W1a|W1b] + [b1|0]   (into g_z, consumed by edge kernel)
        node_gemm<128, 0, 128, false, false><<<148, 256, smem_nb>>>(
            ph, nullptr, pwc, pbc, pz);
        edge_kernel2<<<444, 256, SM_EDGE_BYTES>>>(
            edges, pz, eW2 + l * EH * EH, eb2 + l * EH);
        // z = silu(concat(h, agg) @ nW1 + nb1)
        node_gemm<128, 64, 128, true, false><<<148, 256, smem_na>>>(
            ph, pag, nW1 + l * (HID + EH) * HID, nb1 + l * HID, pz);
        // h = h + (z @ nW2 + nb2)
        node_gemm<128, 0, 128, false, true><<<148, 256, smem_nb>>>(
            pz, nullptr, nW2 + l * HID * HID, nb2 + l * HID, ph);
    }

    node_gemm<128, 0, 64, false, false><<<148, 256, smem_eo>>>(
        ph, nullptr, W_out, b_out, (float*)d_out);
}

// round 5
// speedup vs baseline: 3.0853x; 1.0221x over previous
#include <cuda_runtime.h>
#include <cuda_bf16.h>
#include <cstdint>

// GNN_84421877170708: 4-layer GCL GNN.
// P = h @ [W1a|W1b] per node (fp32 GEMM); edge kernel = gather-add + silu +
// tf32 mma MLP2 + scatter. Round 5: node GEMMs restructured for occupancy
// (K-chunked staging + column-split) -> 2-3 CTAs/SM.

#define N_NODES 50000
#define E_EDGES 800000
#define IN_NF   64
#define HID     128
#define EH      64
#define OUT_NF  64
#define L_LAYERS 4
#define ET      128

__device__ float g_h[N_NODES * HID];
__device__ float g_agg[N_NODES * EH];
__device__ float g_z[N_NODES * HID];
__device__ float g_wcat[HID * HID];
__device__ float g_bcat[HID];

using u64 = unsigned long long;
using u32 = unsigned int;

__device__ __forceinline__ float silu(float v) {
    float h = 0.5f * v, t;
    asm("tanh.approx.f32 %0, %1;" : "=f"(t) : "f"(h));
    return fmaf(h, t, h);
}
__device__ __forceinline__ u32 f2tf32(float f) {
    u32 r; asm("cvt.rna.tf32.f32 %0, %1;" : "=r"(r) : "f"(f)); return r;
}
__device__ __forceinline__ float tf32f(float f) {
    return __uint_as_float(f2tf32(f));
}
__device__ __forceinline__ void mma_tf32(float* c, u32 a0, u32 a1, u32 a2, u32 a3,
                                         u32 b0, u32 b1) {
    asm volatile(
        "mma.sync.aligned.m16n8k8.row.col.f32.tf32.tf32.f32 "
        "{%0,%1,%2,%3}, {%4,%5,%6,%7}, {%8,%9}, {%0,%1,%2,%3};"
        : "+f"(c[0]), "+f"(c[1]), "+f"(c[2]), "+f"(c[3])
        : "r"(a0), "r"(a1), "r"(a2), "r"(a3), "r"(b0), "r"(b1));
}
__device__ __forceinline__ void red2(float* p, float v0, float v1) {
    asm volatile("red.global.add.v2.f32 [%0], {%1,%2};" :: "l"(p), "f"(v0), "f"(v1) : "memory");
}
__device__ __forceinline__ void ffma2(u64& acc, u64 x, u64 w) {
    asm("fma.rn.f32x2 %0, %1, %2, %0;" : "+l"(acc) : "l"(x), "l"(w));
}
__device__ __forceinline__ u64 pack2(float x) {
    u64 r; asm("mov.b64 %0, {%1, %1};" : "=l"(r) : "f"(x)); return r;
}
__device__ __forceinline__ u64 packf2(float a, float b) {
    u64 r; asm("mov.b64 %0, {%1, %2};" : "=l"(r) : "f"(a), "f"(b)); return r;
}
__device__ __forceinline__ float2 unpack2(u64 v) {
    float2 r; asm("mov.b64 {%0, %1}, %2;" : "=f"(r.x), "=f"(r.y) : "l"(v)); return r;
}

// ---------------------------------------------------------------------------
// prep: zero g_agg; repack W1 [256x64] -> g_wcat [128x128], g_bcat = [b1|0]
// ---------------------------------------------------------------------------
__global__ void prep_layer(const float* __restrict__ eW1, const float* __restrict__ b1) {
    int i = blockIdx.x * 256 + threadIdx.x;
    if (i < N_NODES * EH / 4)
        ((float4*)g_agg)[i] = make_float4(0.f, 0.f, 0.f, 0.f);
    if (i < HID * HID) {
        int k = i >> 7, j = i & 127;
        g_wcat[i] = (j < 64) ? eW1[k * 64 + j] : eW1[(k + 128) * 64 + (j - 64)];
    }
    if (i < HID) g_bcat[i] = (i < 64) ? b1[i] : 0.f;
}

// ---------------------------------------------------------------------------
// node_gemm3: out[:, yoff:yoff+64] = act(concat(in1,in2) @ W[:, yoff:yoff+64] + b)
// 256 threads, 8 warps, per-warp 16-node tiles, K chunked by 64.
// smem: ws[KDIM*64] + bs[64] + 8 warps * 64*16 staging.
// ---------------------------------------------------------------------------
template<int KDIM, int W1IN, int NOUT_TOTAL, bool DO_SILU, bool DO_RES>
__global__ void __launch_bounds__(256, 2) node_gemm3(
    const float* __restrict__ in1, const float* __restrict__ in2,
    const float* __restrict__ W, const float* __restrict__ b,
    float* __restrict__ out)
{
    extern __shared__ float fsmem[];
    float* ws = fsmem;                 // [KDIM][64]
    float* bs = ws + KDIM * 64;        // [64]
    float* stg = bs + 64;              // 8 x (64*16)

    const int tid  = threadIdx.x;
    const int warp = tid >> 5;
    const int lane = tid & 31;
    const int yoff = blockIdx.y * 64;

    // weights: 64-col slice
    for (int i = tid * 4; i < KDIM * 64; i += 1024) {
        int k = i >> 6, j = i & 63;
        *(float4*)&ws[i] = *(const float4*)(W + (size_t)k * NOUT_TOTAL + yoff + j);
    }
    if (tid < 64) bs[tid] = b[yoff + tid];
    __syncthreads();

    float* xs = stg + warp * (64 * 16);
    const int p    = lane >> 2;   // 8 col groups of 8
    const int q    = lane & 3;    // 4 node groups of 4
    const int m    = lane >> 1;   // 16 nodes, 2 lanes each
    const int half = lane & 1;

    u64 biasr[4];
#pragma unroll
    for (int g = 0; g < 4; g++)
        biasr[g] = packf2(bs[p * 8 + 2 * g], bs[p * 8 + 2 * g + 1]);

    const int gw     = blockIdx.x * 8 + warp;
    const int nwarps = gridDim.x * 8;
    const int ntiles = N_NODES / 16;

    for (int t = gw; t < ntiles; t += nwarps) {
        const int node = t * 16 + m;
        const float* s1 = in1 + (size_t)node * W1IN;
        const float* s2 = (KDIM > W1IN) ? in2 + (size_t)node * (KDIM - W1IN) : nullptr;

        u64 acc[4][4];
#pragma unroll
        for (int d = 0; d < 4; d++)
#pragma unroll
            for (int g = 0; g < 4; g++) acc[d][g] = biasr[g];

#pragma unroll
        for (int c0 = 0; c0 < KDIM; c0 += 64) {
            // stage chunk [c0, c0+64) transposed: xs[k][16]
            __syncwarp();
#pragma unroll
            for (int i = 0; i < 8; i++) {
                int kk = c0 + half * 32 + i * 4;
                float4 v;
                if (KDIM == W1IN || kk < W1IN) v = *(const float4*)(s1 + kk);
                else                           v = *(const float4*)(s2 + (kk - W1IN));
                int kl = kk - c0;
                xs[(kl + 0) * 16 + m] = v.x;
                xs[(kl + 1) * 16 + m] = v.y;
                xs[(kl + 2) * 16 + m] = v.z;
                xs[(kl + 3) * 16 + m] = v.w;
            }
            __syncwarp();

#pragma unroll 4
            for (int k = 0; k < 64; k++) {
                float4 xv = *(const float4*)&xs[k * 16 + q * 4];
                const ulonglong2* wp = (const ulonglong2*)(ws + (c0 + k) * 64 + p * 8);
                ulonglong2 wa = wp[0];
                ulonglong2 wb = wp[1];
                u64 xp[4] = {pack2(xv.x), pack2(xv.y), pack2(xv.z), pack2(xv.w)};
#pragma unroll
                for (int d = 0; d < 4; d++) {
                    ffma2(acc[d][0], xp[d], wa.x);
                    ffma2(acc[d][1], xp[d], wa.y);
                    ffma2(acc[d][2], xp[d], wb.x);
                    ffma2(acc[d][3], xp[d], wb.y);
                }
            }
        }

#pragma unroll
        for (int d = 0; d < 4; d++) {
            int nn = t * 16 + q * 4 + d;
            float* dst = out + (size_t)nn * NOUT_TOTAL + yoff + p * 8;
#pragma unroll
            for (int g = 0; g < 2; g++) {
                float2 a = unpack2(acc[d][2 * g]);
                float2 c = unpack2(acc[d][2 * g + 1]);
                float4 v = make_float4(a.x, a.y, c.x, c.y);
                if (DO_SILU) {
                    v.x = silu(v.x); v.y = silu(v.y);
                    v.z = silu(v.z); v.w = silu(v.w);
                }
                if (DO_RES) {
                    float4 r = *(const float4*)(dst + g * 4);
                    v.x += r.x; v.y += r.y; v.z += r.z; v.w += r.w;
                }
                *(float4*)(dst + g * 4) = v;
            }
        }
    }
}

// ---------------------------------------------------------------------------
// Edge kernel (unchanged from round 4): gather+silu -> tf32 mma MLP2 -> scatter
// ---------------------------------------------------------------------------
#define SM_IDX  0
#define SM_B2S  128
#define SM_X2   192
#define SM_B2P  (192 + 128 * 66)
#define SM_EDGE_FLOATS (SM_B2P + 8 * 4 * 32 * 4)
#define SM_EDGE_BYTES  (SM_EDGE_FLOATS * 4)

__global__ void __launch_bounds__(256, 3)
edge_kernel2(const int* __restrict__ edges, const float* __restrict__ P,
             const float* __restrict__ W2, const float* __restrict__ b2)
{
    extern __shared__ float sm[];
    int*   idxs = (int*)sm;
    float* b2s  = sm + SM_B2S;
    float* X2   = sm + SM_X2;
    float* B2p  = sm + SM_B2P;

    const int tid  = threadIdx.x;
    const int warp = tid >> 5, lane = tid & 31;
    const int g    = lane >> 2, tig = lane & 3;

    for (int i = tid; i < 8 * 4 * 32; i += 256) {
        int s  = i >> 7;
        int jp = (i >> 5) & 3;
        int ln = i & 31;
        int gg = ln >> 2, tt = ln & 3;
        int k0 = s * 8, n0 = jp * 16;
        float4 v;
        v.x = tf32f(W2[(k0 + tt)     * 64 + n0 + gg]);
        v.y = tf32f(W2[(k0 + tt + 4) * 64 + n0 + gg]);
        v.z = tf32f(W2[(k0 + tt)     * 64 + n0 + 8 + gg]);
        v.w = tf32f(W2[(k0 + tt + 4) * 64 + n0 + 8 + gg]);
        *(float4*)&B2p[i * 4] = v;
    }
    if (tid < 64) b2s[tid] = b2[tid];
    __syncthreads();

    const float* xlo = X2 + (warp * 16 + g) * 66 + tig * 2;
    const float* xhi = xlo + 8 * 66;

    for (int t = blockIdx.x; t < E_EDGES / ET; t += gridDim.x) {
        {
            int e = tid >> 1, half = tid & 1;
            int row  = edges[t * ET + e];
            int coln = edges[E_EDGES + t * ET + e];
            if (half == 0) idxs[e] = row;
            const float4* pa = (const float4*)(P + (size_t)row  * HID + half * 32);
            const float4* pb = (const float4*)(P + (size_t)coln * HID + 64 + half * 32);
            float va[32];
#pragma unroll
            for (int i = 0; i < 8; i++) {
                float4 x = pa[i];
                float4 y = pb[i];
                va[i * 4 + 0] = tf32f(silu(x.x + y.x));
                va[i * 4 + 1] = tf32f(silu(x.y + y.y));
                va[i * 4 + 2] = tf32f(silu(x.z + y.z));
                va[i * 4 + 3] = tf32f(silu(x.w + y.w));
            }
            float* xr = X2 + e * 66;
#pragma unroll
            for (int b = 0; b < 4; b++)
#pragma unroll
                for (int j = 0; j < 4; j++) {
                    float2 v = make_float2(va[(b * 2) * 4 + j], va[(b * 2 + 1) * 4 + j]);
                    *(float2*)&xr[(half * 4 + b) * 8 + j * 2] = v;
                }
        }
        __syncthreads();

        float acc[8][4];
#pragma unroll
        for (int a = 0; a < 8; a++)
#pragma unroll
            for (int c = 0; c < 4; c++) acc[a][c] = 0.f;

#pragma unroll
        for (int s = 0; s < 8; s++) {
            float2 alo = *(const float2*)(xlo + s * 8);
            float2 ahi = *(const float2*)(xhi + s * 8);
            u32 a0 = __float_as_uint(alo.x), a1 = __float_as_uint(ahi.x);
            u32 a2 = __float_as_uint(alo.y), a3 = __float_as_uint(ahi.y);
#pragma unroll
            for (int jp = 0; jp < 4; jp++) {
                float4 bv = *(const float4*)&B2p[((s * 4 + jp) * 32 + lane) * 4];
                mma_tf32(acc[jp * 2 + 0], a0, a1, a2, a3,
                         __float_as_uint(bv.x), __float_as_uint(bv.y));
                mma_tf32(acc[jp * 2 + 1], a0, a1, a2, a3,
                         __float_as_uint(bv.z), __float_as_uint(bv.w));
            }
        }

        {
            int nlo = idxs[warp * 16 + g];
            int nhi = idxs[warp * 16 + g + 8];
            float* dlo = g_agg + (size_t)nlo * EH;
            float* dhi = g_agg + (size_t)nhi * EH;
#pragma unroll
            for (int a = 0; a < 8; a++) {
                int c0 = (a >> 1) * 16 + (a & 1) * 8 + tig * 2;
                red2(dlo + c0, silu(acc[a][0] + b2s[c0]), silu(acc[a][1] + b2s[c0 + 1]));
                red2(dhi + c0, silu(acc[a][2] + b2s[c0]), silu(acc[a][3] + b2s[c0 + 1]));
            }
        }
        __syncthreads();
    }
}

// ---------------------------------------------------------------------------
extern "C" void kernel_launch(void* const* d_in, const int* in_sizes, int n_in,
                              void* d_out, int out_size)
{
    const float* h_in  = (const float*)d_in[0];
    const int*   edges = (const int*)d_in[1];
    const float* W_in  = (const float*)d_in[2];
    const float* b_in  = (const float*)d_in[3];
    const float* eW1   = (const float*)d_in[4];
    const float* eb1   = (const float*)d_in[5];
    const float* eW2   = (const float*)d_in[6];
    const float* eb2   = (const float*)d_in[7];
    const float* nW1   = (const float*)d_in[8];
    const float* nb1   = (const float*)d_in[9];
    const float* nW2   = (const float*)d_in[10];
    const float* nb2   = (const float*)d_in[11];
    const float* W_out = (const float*)d_in[12];
    const float* b_out = (const float*)d_in[13];

    float* ph;   cudaGetSymbolAddress((void**)&ph,   g_h);
    float* pag;  cudaGetSymbolAddress((void**)&pag,  g_agg);
    float* pz;   cudaGetSymbolAddress((void**)&pz,   g_z);
    float* pwc;  cudaGetSymbolAddress((void**)&pwc,  g_wcat);
    float* pbc;  cudaGetSymbolAddress((void**)&pbc,  g_bcat);

    auto smem_of = [](int kdim) { return (kdim * 64 + 64 + 8 * 64 * 16) * 4; };
    const int sm_ei = smem_of(64);    // 49408
    const int sm_p  = smem_of(128);   // 65792
    const int sm_na = smem_of(192);   // 82176

    cudaFuncSetAttribute(edge_kernel2, cudaFuncAttributeMaxDynamicSharedMemorySize, SM_EDGE_BYTES);
    cudaFuncSetAttribute(node_gemm3<64, 64, 128, false, false>,
                         cudaFuncAttributeMaxDynamicSharedMemorySize, sm_ei);
    cudaFuncSetAttribute(node_gemm3<128, 128, 128, false, false>,
                         cudaFuncAttributeMaxDynamicSharedMemorySize, sm_p);
    cudaFuncSetAttribute(node_gemm3<192, 128, 128, true, false>,
                         cudaFuncAttributeMaxDynamicSharedMemorySize, sm_na);
    cudaFuncSetAttribute(node_gemm3<128, 128, 128, false, true>,
                         cudaFuncAttributeMaxDynamicSharedMemorySize, sm_p);
    cudaFuncSetAttribute(node_gemm3<128, 128, 64, false, false>,
                         cudaFuncAttributeMaxDynamicSharedMemorySize, sm_p);

    // embedding_in
    node_gemm3<64, 64, 128, false, false><<<dim3(148, 2), 256, sm_ei>>>(
        h_in, nullptr, W_in, b_in, ph);

    for (int l = 0; l < L_LAYERS; l++) {
        prep_layer<<<(N_NODES * EH / 4 + 255) / 256, 256>>>(
            eW1 + l * 2 * HID * EH, eb1 + l * EH);
        node_gemm3<128, 128, 128, false, false><<<dim3(148, 2), 256, sm_p>>>(
            ph, nullptr, pwc, pbc, pz);
        edge_kernel2<<<444, 256, SM_EDGE_BYTES>>>(
            edges, pz, eW2 + l * EH * EH, eb2 + l * EH);
        node_gemm3<192, 128, 128, true, false><<<dim3(148, 2), 256, sm_na>>>(
            ph, pag, nW1 + l * (HID + EH) * HID, nb1 + l * HID, pz);
        node_gemm3<128, 128, 128, false, true><<<dim3(148, 2), 256, sm_p>>>(
            pz, nullptr, nW2 + l * HID * HID, nb2 + l * HID, ph);
    }

    // embedding_out
    node_gemm3<128, 128, 64, false, false><<<dim3(148, 1), 256, sm_p>>>(
        ph, nullptr, W_out, b_out, (float*)d_out);
}

// round 6
// speedup vs baseline: 3.3510x; 1.0861x over previous
#include <cuda_runtime.h>
#include <cuda_bf16.h>
#include <cstdint>

// GNN_84421877170708: 4-layer GCL GNN.
// Round 6: counting-sort edges by row (once per launch) to fix L1 gather/
// scatter locality in the edge kernel; red.global.add.v4 scatter.

#define N_NODES 50000
#define E_EDGES 800000
#define IN_NF   64
#define HID     128
#define EH      64
#define OUT_NF  64
#define L_LAYERS 4
#define ET      128
#define SCAN_BLOCKS ((N_NODES + 255) / 256)   // 196

__device__ float g_h[N_NODES * HID];
__device__ float g_agg[N_NODES * EH];
__device__ float g_z[N_NODES * HID];
__device__ float g_wcat[HID * HID];
__device__ float g_bcat[HID];

__device__ int g_deg[N_NODES];
__device__ int g_base[N_NODES];
__device__ int g_cursor[N_NODES];
__device__ int g_bsums[256];
__device__ int g_srow[E_EDGES];
__device__ int g_scol[E_EDGES];

using u64 = unsigned long long;
using u32 = unsigned int;

__device__ __forceinline__ float silu(float v) {
    float h = 0.5f * v, t;
    asm("tanh.approx.f32 %0, %1;" : "=f"(t) : "f"(h));
    return fmaf(h, t, h);
}
__device__ __forceinline__ u32 f2tf32(float f) {
    u32 r; asm("cvt.rna.tf32.f32 %0, %1;" : "=r"(r) : "f"(f)); return r;
}
__device__ __forceinline__ float tf32f(float f) {
    return __uint_as_float(f2tf32(f));
}
__device__ __forceinline__ void mma_tf32(float* c, u32 a0, u32 a1, u32 a2, u32 a3,
                                         u32 b0, u32 b1) {
    asm volatile(
        "mma.sync.aligned.m16n8k8.row.col.f32.tf32.tf32.f32 "
        "{%0,%1,%2,%3}, {%4,%5,%6,%7}, {%8,%9}, {%0,%1,%2,%3};"
        : "+f"(c[0]), "+f"(c[1]), "+f"(c[2]), "+f"(c[3])
        : "r"(a0), "r"(a1), "r"(a2), "r"(a3), "r"(b0), "r"(b1));
}
__device__ __forceinline__ void red4(float* p, float a, float b, float c, float d) {
    asm volatile("red.global.add.v4.f32 [%0], {%1,%2,%3,%4};"
                 :: "l"(p), "f"(a), "f"(b), "f"(c), "f"(d) : "memory");
}
__device__ __forceinline__ void ffma2(u64& acc, u64 x, u64 w) {
    asm("fma.rn.f32x2 %0, %1, %2, %0;" : "+l"(acc) : "l"(x), "l"(w));
}
__device__ __forceinline__ u64 pack2(float x) {
    u64 r; asm("mov.b64 %0, {%1, %1};" : "=l"(r) : "f"(x)); return r;
}
__device__ __forceinline__ u64 packf2(float a, float b) {
    u64 r; asm("mov.b64 %0, {%1, %2};" : "=l"(r) : "f"(a), "f"(b)); return r;
}
__device__ __forceinline__ float2 unpack2(u64 v) {
    float2 r; asm("mov.b64 {%0, %1}, %2;" : "=f"(r.x), "=f"(r.y) : "l"(v)); return r;
}

// ---------------------------------------------------------------------------
// counting sort of edges by row (executed once per launch)
// ---------------------------------------------------------------------------
__global__ void k_zero_deg() {
    int i = blockIdx.x * 256 + threadIdx.x;
    if (i < N_NODES) { g_deg[i] = 0; g_cursor[i] = 0; }
}
__global__ void k_hist(const int* __restrict__ edges) {
    int e = blockIdx.x * 256 + threadIdx.x;
    if (e < E_EDGES) atomicAdd(&g_deg[edges[e]], 1);
}
__global__ void k_scan1() {
    __shared__ int s[256];
    int i = blockIdx.x * 256 + threadIdx.x;
    int v = (i < N_NODES) ? g_deg[i] : 0;
    s[threadIdx.x] = v;
    __syncthreads();
#pragma unroll
    for (int o = 1; o < 256; o <<= 1) {
        int t = (threadIdx.x >= o) ? s[threadIdx.x - o] : 0;
        __syncthreads();
        s[threadIdx.x] += t;
        __syncthreads();
    }
    if (i < N_NODES) g_base[i] = s[threadIdx.x] - v;
    if (threadIdx.x == 255) g_bsums[blockIdx.x] = s[255];
}
__global__ void k_scan2() {
    __shared__ int s[256];
    int i = threadIdx.x;
    int v = (i < SCAN_BLOCKS) ? g_bsums[i] : 0;
    s[i] = v;
    __syncthreads();
#pragma unroll
    for (int o = 1; o < 256; o <<= 1) {
        int t = (i >= o) ? s[i - o] : 0;
        __syncthreads();
        s[i] += t;
        __syncthreads();
    }
    g_bsums[i] = s[i] - v;
}
__global__ void k_scan3() {
    int i = blockIdx.x * 256 + threadIdx.x;
    if (i < N_NODES) g_base[i] += g_bsums[blockIdx.x];
}
__global__ void k_sort_scatter(const int* __restrict__ edges) {
    int e = blockIdx.x * 256 + threadIdx.x;
    if (e < E_EDGES) {
        int r = edges[e], c = edges[E_EDGES + e];
        int pos = g_base[r] + atomicAdd(&g_cursor[r], 1);
        g_srow[pos] = r;
        g_scol[pos] = c;
    }
}

// ---------------------------------------------------------------------------
// prep: zero g_agg; repack W1 [256x64] -> g_wcat [128x128], g_bcat = [b1|0]
// ---------------------------------------------------------------------------
__global__ void prep_layer(const float* __restrict__ eW1, const float* __restrict__ b1) {
    int i = blockIdx.x * 256 + threadIdx.x;
    if (i < N_NODES * EH / 4)
        ((float4*)g_agg)[i] = make_float4(0.f, 0.f, 0.f, 0.f);
    if (i < HID * HID) {
        int k = i >> 7, j = i & 127;
        g_wcat[i] = (j < 64) ? eW1[k * 64 + j] : eW1[(k + 128) * 64 + (j - 64)];
    }
    if (i < HID) g_bcat[i] = (i < 64) ? b1[i] : 0.f;
}

// ---------------------------------------------------------------------------
// node_gemm3 (unchanged from round 5)
// ---------------------------------------------------------------------------
template<int KDIM, int W1IN, int NOUT_TOTAL, bool DO_SILU, bool DO_RES>
__global__ void __launch_bounds__(256, 2) node_gemm3(
    const float* __restrict__ in1, const float* __restrict__ in2,
    const float* __restrict__ W, const float* __restrict__ b,
    float* __restrict__ out)
{
    extern __shared__ float fsmem[];
    float* ws = fsmem;
    float* bs = ws + KDIM * 64;
    float* stg = bs + 64;

    const int tid  = threadIdx.x;
    const int warp = tid >> 5;
    const int lane = tid & 31;
    const int yoff = blockIdx.y * 64;

    for (int i = tid * 4; i < KDIM * 64; i += 1024) {
        int k = i >> 6, j = i & 63;
        *(float4*)&ws[i] = *(const float4*)(W + (size_t)k * NOUT_TOTAL + yoff + j);
    }
    if (tid < 64) bs[tid] = b[yoff + tid];
    __syncthreads();

    float* xs = stg + warp * (64 * 16);
    const int p    = lane >> 2;
    const int q    = lane & 3;
    const int m    = lane >> 1;
    const int half = lane & 1;

    u64 biasr[4];
#pragma unroll
    for (int g = 0; g < 4; g++)
        biasr[g] = packf2(bs[p * 8 + 2 * g], bs[p * 8 + 2 * g + 1]);

    const int gw     = blockIdx.x * 8 + warp;
    const int nwarps = gridDim.x * 8;
    const int ntiles = N_NODES / 16;

    for (int t = gw; t < ntiles; t += nwarps) {
        const int node = t * 16 + m;
        const float* s1 = in1 + (size_t)node * W1IN;
        const float* s2 = (KDIM > W1IN) ? in2 + (size_t)node * (KDIM - W1IN) : nullptr;

        u64 acc[4][4];
#pragma unroll
        for (int d = 0; d < 4; d++)
#pragma unroll
            for (int g = 0; g < 4; g++) acc[d][g] = biasr[g];

#pragma unroll
        for (int c0 = 0; c0 < KDIM; c0 += 64) {
            __syncwarp();
#pragma unroll
            for (int i = 0; i < 8; i++) {
                int kk = c0 + half * 32 + i * 4;
                float4 v;
                if (KDIM == W1IN || kk < W1IN) v = *(const float4*)(s1 + kk);
                else                           v = *(const float4*)(s2 + (kk - W1IN));
                int kl = kk - c0;
                xs[(kl + 0) * 16 + m] = v.x;
                xs[(kl + 1) * 16 + m] = v.y;
                xs[(kl + 2) * 16 + m] = v.z;
                xs[(kl + 3) * 16 + m] = v.w;
            }
            __syncwarp();

#pragma unroll 4
            for (int k = 0; k < 64; k++) {
                float4 xv = *(const float4*)&xs[k * 16 + q * 4];
                const ulonglong2* wp = (const ulonglong2*)(ws + (c0 + k) * 64 + p * 8);
                ulonglong2 wa = wp[0];
                ulonglong2 wb = wp[1];
                u64 xp[4] = {pack2(xv.x), pack2(xv.y), pack2(xv.z), pack2(xv.w)};
#pragma unroll
                for (int d = 0; d < 4; d++) {
                    ffma2(acc[d][0], xp[d], wa.x);
                    ffma2(acc[d][1], xp[d], wa.y);
                    ffma2(acc[d][2], xp[d], wb.x);
                    ffma2(acc[d][3], xp[d], wb.y);
                }
            }
        }

#pragma unroll
        for (int d = 0; d < 4; d++) {
            int nn = t * 16 + q * 4 + d;
            float* dst = out + (size_t)nn * NOUT_TOTAL + yoff + p * 8;
#pragma unroll
            for (int g = 0; g < 2; g++) {
                float2 a = unpack2(acc[d][2 * g]);
                float2 c = unpack2(acc[d][2 * g + 1]);
                float4 v = make_float4(a.x, a.y, c.x, c.y);
                if (DO_SILU) {
                    v.x = silu(v.x); v.y = silu(v.y);
                    v.z = silu(v.z); v.w = silu(v.w);
                }
                if (DO_RES) {
                    float4 r = *(const float4*)(dst + g * 4);
                    v.x += r.x; v.y += r.y; v.z += r.z; v.w += r.w;
                }
                *(float4*)(dst + g * 4) = v;
            }
        }
    }
}

// ---------------------------------------------------------------------------
// Edge kernel: sorted edges; gather+silu -> tf32 mma MLP2 -> red.v4 scatter.
// B-fragment columns interleaved so each lane owns 4 consecutive output cols:
//   group gp (16 cols at gp*16): frag A -> cols 4*tig+{0,1}, frag B -> +{2,3}.
// ---------------------------------------------------------------------------
#define SM_IDX  0
#define SM_B2S  128
#define SM_X2   192
#define SM_B2P  (192 + 128 * 66)
#define SM_EDGE_FLOATS (SM_B2P + 8 * 4 * 32 * 4)
#define SM_EDGE_BYTES  (SM_EDGE_FLOATS * 4)

__global__ void __launch_bounds__(256, 3)
edge_kernel2(const int* __restrict__ srow, const int* __restrict__ scol,
             const float* __restrict__ P,
             const float* __restrict__ W2, const float* __restrict__ b2)
{
    extern __shared__ float sm[];
    int*   idxs = (int*)sm;
    float* b2s  = sm + SM_B2S;
    float* X2   = sm + SM_X2;
    float* B2p  = sm + SM_B2P;

    const int tid  = threadIdx.x;
    const int warp = tid >> 5, lane = tid & 31;
    const int g    = lane >> 2, tig = lane & 3;

    // prepack W2, column-interleaved for v4 epilogue
    for (int i = tid; i < 8 * 4 * 32; i += 256) {
        int s  = i >> 7;
        int gp = (i >> 5) & 3;
        int ln = i & 31;
        int gg = ln >> 2, tt = ln & 3;
        int k0 = s * 8;
        int nA = gp * 16 + (gg >> 1) * 4 + (gg & 1);   // frag A physical col
        int nB = nA + 2;                               // frag B physical col
        float4 v;
        v.x = tf32f(W2[(k0 + tt)     * 64 + nA]);
        v.y = tf32f(W2[(k0 + tt + 4) * 64 + nA]);
        v.z = tf32f(W2[(k0 + tt)     * 64 + nB]);
        v.w = tf32f(W2[(k0 + tt + 4) * 64 + nB]);
        *(float4*)&B2p[i * 4] = v;
    }
    if (tid < 64) b2s[tid] = b2[tid];
    __syncthreads();

    const float* xlo = X2 + (warp * 16 + g) * 66 + tig * 2;
    const float* xhi = xlo + 8 * 66;

    for (int t = blockIdx.x; t < E_EDGES / ET; t += gridDim.x) {
        // ---- gather + silu -> X2 (frag-interleaved tf32) ----
        {
            int e = tid >> 1, half = tid & 1;
            int row  = srow[t * ET + e];
            int coln = scol[t * ET + e];
            if (half == 0) idxs[e] = row;
            const float4* pa = (const float4*)(P + (size_t)row  * HID + half * 32);
            const float4* pb = (const float4*)(P + (size_t)coln * HID + 64 + half * 32);
            float va[32];
#pragma unroll
            for (int i = 0; i < 8; i++) {
                float4 x = pa[i];
                float4 y = pb[i];
                va[i * 4 + 0] = tf32f(silu(x.x + y.x));
                va[i * 4 + 1] = tf32f(silu(x.y + y.y));
                va[i * 4 + 2] = tf32f(silu(x.z + y.z));
                va[i * 4 + 3] = tf32f(silu(x.w + y.w));
            }
            float* xr = X2 + e * 66;
#pragma unroll
            for (int b = 0; b < 4; b++)
#pragma unroll
                for (int j = 0; j < 4; j++) {
                    float2 v = make_float2(va[(b * 2) * 4 + j], va[(b * 2 + 1) * 4 + j]);
                    *(float2*)&xr[(half * 4 + b) * 8 + j * 2] = v;
                }
        }
        __syncthreads();

        // ---- MLP2 MMA ----
        float acc[8][4];
#pragma unroll
        for (int a = 0; a < 8; a++)
#pragma unroll
            for (int c = 0; c < 4; c++) acc[a][c] = 0.f;

#pragma unroll
        for (int s = 0; s < 8; s++) {
            float2 alo = *(const float2*)(xlo + s * 8);
            float2 ahi = *(const float2*)(xhi + s * 8);
            u32 a0 = __float_as_uint(alo.x), a1 = __float_as_uint(ahi.x);
            u32 a2 = __float_as_uint(alo.y), a3 = __float_as_uint(ahi.y);
#pragma unroll
            for (int gp = 0; gp < 4; gp++) {
                float4 bv = *(const float4*)&B2p[((s * 4 + gp) * 32 + lane) * 4];
                mma_tf32(acc[gp * 2 + 0], a0, a1, a2, a3,
                         __float_as_uint(bv.x), __float_as_uint(bv.y));
                mma_tf32(acc[gp * 2 + 1], a0, a1, a2, a3,
                         __float_as_uint(bv.z), __float_as_uint(bv.w));
            }
        }

        // ---- epilogue: silu + red.v4 scatter ----
        {
            int nlo = idxs[warp * 16 + g];
            int nhi = idxs[warp * 16 + g + 8];
            float* dlo = g_agg + (size_t)nlo * EH;
            float* dhi = g_agg + (size_t)nhi * EH;
#pragma unroll
            for (int gp = 0; gp < 4; gp++) {
                int c0 = gp * 16 + tig * 4;
                red4(dlo + c0,
                     silu(acc[gp*2][0]   + b2s[c0]),     silu(acc[gp*2][1]   + b2s[c0+1]),
                     silu(acc[gp*2+1][0] + b2s[c0+2]),   silu(acc[gp*2+1][1] + b2s[c0+3]));
                red4(dhi + c0,
                     silu(acc[gp*2][2]   + b2s[c0]),     silu(acc[gp*2][3]   + b2s[c0+1]),
                     silu(acc[gp*2+1][2] + b2s[c0+2]),   silu(acc[gp*2+1][3] + b2s[c0+3]));
            }
        }
        __syncthreads();
    }
}

// ---------------------------------------------------------------------------
extern "C" void kernel_launch(void* const* d_in, const int* in_sizes, int n_in,
                              void* d_out, int out_size)
{
    const float* h_in  = (const float*)d_in[0];
    const int*   edges = (const int*)d_in[1];
    const float* W_in  = (const float*)d_in[2];
    const float* b_in  = (const float*)d_in[3];
    const float* eW1   = (const float*)d_in[4];
    const float* eb1   = (const float*)d_in[5];
    const float* eW2   = (const float*)d_in[6];
    const float* eb2   = (const float*)d_in[7];
    const float* nW1   = (const float*)d_in[8];
    const float* nb1   = (const float*)d_in[9];
    const float* nW2   = (const float*)d_in[10];
    const float* nb2   = (const float*)d_in[11];
    const float* W_out = (const float*)d_in[12];
    const float* b_out = (const float*)d_in[13];

    float* ph;   cudaGetSymbolAddress((void**)&ph,   g_h);
    float* pag;  cudaGetSymbolAddress((void**)&pag,  g_agg);
    float* pz;   cudaGetSymbolAddress((void**)&pz,   g_z);
    float* pwc;  cudaGetSymbolAddress((void**)&pwc,  g_wcat);
    float* pbc;  cudaGetSymbolAddress((void**)&pbc,  g_bcat);
    int* psrow;  cudaGetSymbolAddress((void**)&psrow, g_srow);
    int* pscol;  cudaGetSymbolAddress((void**)&pscol, g_scol);

    auto smem_of = [](int kdim) { return (kdim * 64 + 64 + 8 * 64 * 16) * 4; };
    const int sm_ei = smem_of(64);
    const int sm_p  = smem_of(128);
    const int sm_na = smem_of(192);

    cudaFuncSetAttribute(edge_kernel2, cudaFuncAttributeMaxDynamicSharedMemorySize, SM_EDGE_BYTES);
    cudaFuncSetAttribute(node_gemm3<64, 64, 128, false, false>,
                         cudaFuncAttributeMaxDynamicSharedMemorySize, sm_ei);
    cudaFuncSetAttribute(node_gemm3<128, 128, 128, false, false>,
                         cudaFuncAttributeMaxDynamicSharedMemorySize, sm_p);
    cudaFuncSetAttribute(node_gemm3<192, 128, 128, true, false>,
                         cudaFuncAttributeMaxDynamicSharedMemorySize, sm_na);
    cudaFuncSetAttribute(node_gemm3<128, 128, 128, false, true>,
                         cudaFuncAttributeMaxDynamicSharedMemorySize, sm_p);
    cudaFuncSetAttribute(node_gemm3<128, 128, 64, false, false>,
                         cudaFuncAttributeMaxDynamicSharedMemorySize, sm_p);

    const int EB = (E_EDGES + 255) / 256;

    // ---- sort edges by row (overlaps nothing; runs before layer loop) ----
    k_zero_deg<<<SCAN_BLOCKS, 256>>>();
    k_hist<<<EB, 256>>>(edges);
    k_scan1<<<SCAN_BLOCKS, 256>>>();
    k_scan2<<<1, 256>>>();
    k_scan3<<<SCAN_BLOCKS, 256>>>();
    k_sort_scatter<<<EB, 256>>>(edges);

    // embedding_in
    node_gemm3<64, 64, 128, false, false><<<dim3(148, 2), 256, sm_ei>>>(
        h_in, nullptr, W_in, b_in, ph);

    for (int l = 0; l < L_LAYERS; l++) {
        prep_layer<<<(N_NODES * EH / 4 + 255) / 256, 256>>>(
            eW1 + l * 2 * HID * EH, eb1 + l * EH);
        node_gemm3<128, 128, 128, false, false><<<dim3(148, 2), 256, sm_p>>>(
            ph, nullptr, pwc, pbc, pz);
        edge_kernel2<<<444, 256, SM_EDGE_BYTES>>>(
            psrow, pscol, pz, eW2 + l * EH * EH, eb2 + l * EH);
        node_gemm3<192, 128, 128, true, false><<<dim3(148, 2), 256, sm_na>>>(
            ph, pag, nW1 + l * (HID + EH) * HID, nb1 + l * HID, pz);
        node_gemm3<128, 128, 128, false, true><<<dim3(148, 2), 256, sm_p>>>(
            pz, nullptr, nW2 + l * HID * HID, nb2 + l * HID, ph);
    }

    // embedding_out
    node_gemm3<128, 128, 64, false, false><<<dim3(148, 1), 256, sm_p>>>(
        ph, nullptr, W_out, b_out, (float*)d_out);
}

// round 7
// speedup vs baseline: 3.9457x; 1.1775x over previous
#include <cuda_runtime.h>
#include <cuda_bf16.h>
#include <cstdint>

// GNN_84421877170708: 4-layer GCL GNN. Round 7:
//  - P-gemm and nW1-gemm moved to tf32 mma.sync (128-node tiles), reusing the
//    proven edge-kernel fragment layout; nb (residual) + embeddings stay fp32.
//  - X staging stride 66 -> 82 (2-way-optimal LDS banking) in all mma kernels.

#define N_NODES 50000
#define E_EDGES 800000
#define IN_NF   64
#define HID     128
#define EH      64
#define OUT_NF  64
#define L_LAYERS 4
#define ET      128
#define XSTR    82            // staging row stride (mod 32 == 18: 2-way banks)
#define SCAN_BLOCKS ((N_NODES + 255) / 256)

__device__ float g_h[N_NODES * HID];
__device__ float g_agg[N_NODES * EH];
__device__ float g_z[N_NODES * HID];
__device__ float g_wcat[HID * HID];
__device__ float g_bcat[HID];

__device__ int g_deg[N_NODES];
__device__ int g_base[N_NODES];
__device__ int g_cursor[N_NODES];
__device__ int g_bsums[256];
__device__ int g_srow[E_EDGES];
__device__ int g_scol[E_EDGES];

using u64 = unsigned long long;
using u32 = unsigned int;

__device__ __forceinline__ float silu(float v) {
    float h = 0.5f * v, t;
    asm("tanh.approx.f32 %0, %1;" : "=f"(t) : "f"(h));
    return fmaf(h, t, h);
}
__device__ __forceinline__ u32 f2tf32(float f) {
    u32 r; asm("cvt.rna.tf32.f32 %0, %1;" : "=r"(r) : "f"(f)); return r;
}
__device__ __forceinline__ float tf32f(float f) {
    return __uint_as_float(f2tf32(f));
}
__device__ __forceinline__ void mma_tf32(float* c, u32 a0, u32 a1, u32 a2, u32 a3,
                                         u32 b0, u32 b1) {
    asm volatile(
        "mma.sync.aligned.m16n8k8.row.col.f32.tf32.tf32.f32 "
        "{%0,%1,%2,%3}, {%4,%5,%6,%7}, {%8,%9}, {%0,%1,%2,%3};"
        : "+f"(c[0]), "+f"(c[1]), "+f"(c[2]), "+f"(c[3])
        : "r"(a0), "r"(a1), "r"(a2), "r"(a3), "r"(b0), "r"(b1));
}
__device__ __forceinline__ void red4(float* p, float a, float b, float c, float d) {
    asm volatile("red.global.add.v4.f32 [%0], {%1,%2,%3,%4};"
                 :: "l"(p), "f"(a), "f"(b), "f"(c), "f"(d) : "memory");
}
__device__ __forceinline__ void ffma2(u64& acc, u64 x, u64 w) {
    asm("fma.rn.f32x2 %0, %1, %2, %0;" : "+l"(acc) : "l"(x), "l"(w));
}
__device__ __forceinline__ u64 pack2(float x) {
    u64 r; asm("mov.b64 %0, {%1, %1};" : "=l"(r) : "f"(x)); return r;
}
__device__ __forceinline__ u64 packf2(float a, float b) {
    u64 r; asm("mov.b64 %0, {%1, %2};" : "=l"(r) : "f"(a), "f"(b)); return r;
}
__device__ __forceinline__ float2 unpack2(u64 v) {
    float2 r; asm("mov.b64 {%0, %1}, %2;" : "=f"(r.x), "=f"(r.y) : "l"(v)); return r;
}

// ---------------------------------------------------------------------------
// counting sort of edges by row
// ---------------------------------------------------------------------------
__global__ void k_zero_deg() {
    int i = blockIdx.x * 256 + threadIdx.x;
    if (i < N_NODES) { g_deg[i] = 0; g_cursor[i] = 0; }
}
__global__ void k_hist(const int* __restrict__ edges) {
    int e = blockIdx.x * 256 + threadIdx.x;
    if (e < E_EDGES) atomicAdd(&g_deg[edges[e]], 1);
}
__global__ void k_scan1() {
    __shared__ int s[256];
    int i = blockIdx.x * 256 + threadIdx.x;
    int v = (i < N_NODES) ? g_deg[i] : 0;
    s[threadIdx.x] = v;
    __syncthreads();
#pragma unroll
    for (int o = 1; o < 256; o <<= 1) {
        int t = (threadIdx.x >= o) ? s[threadIdx.x - o] : 0;
        __syncthreads();
        s[threadIdx.x] += t;
        __syncthreads();
    }
    if (i < N_NODES) g_base[i] = s[threadIdx.x] - v;
    if (threadIdx.x == 255) g_bsums[blockIdx.x] = s[255];
}
__global__ void k_scan2() {
    __shared__ int s[256];
    int i = threadIdx.x;
    int v = (i < SCAN_BLOCKS) ? g_bsums[i] : 0;
    s[i] = v;
    __syncthreads();
#pragma unroll
    for (int o = 1; o < 256; o <<= 1) {
        int t = (i >= o) ? s[i - o] : 0;
        __syncthreads();
        s[i] += t;
        __syncthreads();
    }
    g_bsums[i] = s[i] - v;
}
__global__ void k_scan3() {
    int i = blockIdx.x * 256 + threadIdx.x;
    if (i < N_NODES) g_base[i] += g_bsums[blockIdx.x];
}
__global__ void k_sort_scatter(const int* __restrict__ edges) {
    int e = blockIdx.x * 256 + threadIdx.x;
    if (e < E_EDGES) {
        int r = edges[e], c = edges[E_EDGES + e];
        int pos = g_base[r] + atomicAdd(&g_cursor[r], 1);
        g_srow[pos] = r;
        g_scol[pos] = c;
    }
}

// ---------------------------------------------------------------------------
__global__ void prep_layer(const float* __restrict__ eW1, const float* __restrict__ b1) {
    int i = blockIdx.x * 256 + threadIdx.x;
    if (i < N_NODES * EH / 4)
        ((float4*)g_agg)[i] = make_float4(0.f, 0.f, 0.f, 0.f);
    if (i < HID * HID) {
        int k = i >> 7, j = i & 127;
        g_wcat[i] = (j < 64) ? eW1[k * 64 + j] : eW1[(k + 128) * 64 + (j - 64)];
    }
    if (i < HID) g_bcat[i] = (i < 64) ? b1[i] : 0.f;
}

// ---------------------------------------------------------------------------
// node_mma: out[:, yoff:yoff+64] = act(concat(in1,in2) @ W[:, yoff:+64] + b)
// tf32 mma.sync, 128-node tiles, 8 warps (warp mg -> rows mg*16..+15).
// SMEM: bs[64] | X[128*XSTR] | Bp[(KDIM/8)*4*32*4]
// ---------------------------------------------------------------------------
template<int KDIM, int W1IN, bool DO_SILU>
__global__ void __launch_bounds__(256, 2) node_mma(
    const float* __restrict__ in1, const float* __restrict__ in2,
    const float* __restrict__ W, const float* __restrict__ b,
    float* __restrict__ out)
{
    constexpr int NSTEP = KDIM / 8;
    extern __shared__ float sm[];
    float* bs = sm;
    float* X  = sm + 64;
    float* Bp = X + 128 * XSTR;

    const int tid  = threadIdx.x;
    const int warp = tid >> 5, lane = tid & 31;
    const int g    = lane >> 2, tig = lane & 3;
    const int yoff = blockIdx.y * 64;

    // prepack W slice into per-lane fragment order (col-interleaved for v4)
    for (int i = tid; i < NSTEP * 4 * 32; i += 256) {
        int s  = i >> 7;
        int gp = (i >> 5) & 3;
        int ln = i & 31;
        int gg = ln >> 2, tt = ln & 3;
        int k0 = s * 8;
        int nA = yoff + gp * 16 + (gg >> 1) * 4 + (gg & 1);
        int nB = nA + 2;
        float4 v;
        v.x = tf32f(W[(size_t)(k0 + tt)     * HID + nA]);
        v.y = tf32f(W[(size_t)(k0 + tt + 4) * HID + nA]);
        v.z = tf32f(W[(size_t)(k0 + tt)     * HID + nB]);
        v.w = tf32f(W[(size_t)(k0 + tt + 4) * HID + nB]);
        *(float4*)&Bp[i * 4] = v;
    }
    if (tid < 64) bs[tid] = b[yoff + tid];

    const float* xlo = X + (warp * 16 + g) * XSTR + tig * 2;
    const float* xhi = xlo + 8 * XSTR;
    const int e  = tid >> 1;       // staging row 0..127
    const int hf = tid & 1;        // 32-feature half within 64-chunk

    const int NTILES = (N_NODES + 127) / 128;
    for (int t = blockIdx.x; t < NTILES; t += gridDim.x) {
        const int tb = t * 128;
        int node = tb + e;
        if (node >= N_NODES) node = 0;   // harmless read; store guarded below

        float acc[8][4];
#pragma unroll
        for (int a = 0; a < 8; a++)
#pragma unroll
            for (int c = 0; c < 4; c++) acc[a][c] = 0.f;

#pragma unroll
        for (int c0 = 0; c0 < KDIM; c0 += 64) {
            __syncthreads();   // prev chunk consumed by all warps
            {
                const int kb = c0 + hf * 32;
                const float4* src;
                if (KDIM == W1IN || kb < W1IN)
                    src = (const float4*)(in1 + (size_t)node * W1IN + kb);
                else
                    src = (const float4*)(in2 + (size_t)node * (KDIM - W1IN) + (kb - W1IN));
                float va[32];
#pragma unroll
                for (int i = 0; i < 8; i++) {
                    float4 v = src[i];
                    va[i * 4 + 0] = tf32f(v.x);
                    va[i * 4 + 1] = tf32f(v.y);
                    va[i * 4 + 2] = tf32f(v.z);
                    va[i * 4 + 3] = tf32f(v.w);
                }
                float* xr = X + e * XSTR;
#pragma unroll
                for (int bb = 0; bb < 4; bb++)
#pragma unroll
                    for (int j = 0; j < 4; j++) {
                        float2 v = make_float2(va[(bb * 2) * 4 + j], va[(bb * 2 + 1) * 4 + j]);
                        *(float2*)&xr[(hf * 4 + bb) * 8 + j * 2] = v;
                    }
            }
            __syncthreads();

#pragma unroll
            for (int s8 = 0; s8 < 8; s8++) {
                const int s = (c0 >> 3) + s8;
                float2 alo = *(const float2*)(xlo + s8 * 8);
                float2 ahi = *(const float2*)(xhi + s8 * 8);
                u32 a0 = __float_as_uint(alo.x), a1 = __float_as_uint(ahi.x);
                u32 a2 = __float_as_uint(alo.y), a3 = __float_as_uint(ahi.y);
#pragma unroll
                for (int gp = 0; gp < 4; gp++) {
                    float4 bv = *(const float4*)&Bp[((s * 4 + gp) * 32 + lane) * 4];
                    mma_tf32(acc[gp * 2 + 0], a0, a1, a2, a3,
                             __float_as_uint(bv.x), __float_as_uint(bv.y));
                    mma_tf32(acc[gp * 2 + 1], a0, a1, a2, a3,
                             __float_as_uint(bv.z), __float_as_uint(bv.w));
                }
            }
        }

        // epilogue: bias (+silu) -> float4 stores, tail-guarded
        {
            int r0 = tb + warp * 16 + g;
            int r1 = r0 + 8;
#pragma unroll
            for (int gp = 0; gp < 4; gp++) {
                int c0 = gp * 16 + tig * 4;
                float4 v0 = make_float4(acc[gp*2][0]   + bs[c0],
                                        acc[gp*2][1]   + bs[c0+1],
                                        acc[gp*2+1][0] + bs[c0+2],
                                        acc[gp*2+1][1] + bs[c0+3]);
                float4 v1 = make_float4(acc[gp*2][2]   + bs[c0],
                                        acc[gp*2][3]   + bs[c0+1],
                                        acc[gp*2+1][2] + bs[c0+2],
                                        acc[gp*2+1][3] + bs[c0+3]);
                if (DO_SILU) {
                    v0.x = silu(v0.x); v0.y = silu(v0.y); v0.z = silu(v0.z); v0.w = silu(v0.w);
                    v1.x = silu(v1.x); v1.y = silu(v1.y); v1.z = silu(v1.z); v1.w = silu(v1.w);
                }
                if (r0 < N_NODES) *(float4*)(out + (size_t)r0 * HID + yoff + c0) = v0;
                if (r1 < N_NODES) *(float4*)(out + (size_t)r1 * HID + yoff + c0) = v1;
            }
        }
    }
}

// ---------------------------------------------------------------------------
// node_gemm3 (fp32, for residual nb + embeddings)
// ---------------------------------------------------------------------------
template<int KDIM, int W1IN, int NOUT_TOTAL, bool DO_SILU, bool DO_RES>
__global__ void __launch_bounds__(256, 2) node_gemm3(
    const float* __restrict__ in1, const float* __restrict__ in2,
    const float* __restrict__ W, const float* __restrict__ b,
    float* __restrict__ out)
{
    extern __shared__ float fsmem[];
    float* ws = fsmem;
    float* bs = ws + KDIM * 64;
    float* stg = bs + 64;

    const int tid  = threadIdx.x;
    const int warp = tid >> 5;
    const int lane = tid & 31;
    const int yoff = blockIdx.y * 64;

    for (int i = tid * 4; i < KDIM * 64; i += 1024) {
        int k = i >> 6, j = i & 63;
        *(float4*)&ws[i] = *(const float4*)(W + (size_t)k * NOUT_TOTAL + yoff + j);
    }
    if (tid < 64) bs[tid] = b[yoff + tid];
    __syncthreads();

    float* xs = stg + warp * (64 * 16);
    const int p    = lane >> 2;
    const int q    = lane & 3;
    const int m    = lane >> 1;
    const int half = lane & 1;

    u64 biasr[4];
#pragma unroll
    for (int g = 0; g < 4; g++)
        biasr[g] = packf2(bs[p * 8 + 2 * g], bs[p * 8 + 2 * g + 1]);

    const int gw     = blockIdx.x * 8 + warp;
    const int nwarps = gridDim.x * 8;
    const int ntiles = N_NODES / 16;

    for (int t = gw; t < ntiles; t += nwarps) {
        const int node = t * 16 + m;
        const float* s1 = in1 + (size_t)node * W1IN;
        const float* s2 = (KDIM > W1IN) ? in2 + (size_t)node * (KDIM - W1IN) : nullptr;

        u64 acc[4][4];
#pragma unroll
        for (int d = 0; d < 4; d++)
#pragma unroll
            for (int g = 0; g < 4; g++) acc[d][g] = biasr[g];

#pragma unroll
        for (int c0 = 0; c0 < KDIM; c0 += 64) {
            __syncwarp();
#pragma unroll
            for (int i = 0; i < 8; i++) {
                int kk = c0 + half * 32 + i * 4;
                float4 v;
                if (KDIM == W1IN || kk < W1IN) v = *(const float4*)(s1 + kk);
                else                           v = *(const float4*)(s2 + (kk - W1IN));
                int kl = kk - c0;
                xs[(kl + 0) * 16 + m] = v.x;
                xs[(kl + 1) * 16 + m] = v.y;
                xs[(kl + 2) * 16 + m] = v.z;
                xs[(kl + 3) * 16 + m] = v.w;
            }
            __syncwarp();

#pragma unroll 4
            for (int k = 0; k < 64; k++) {
                float4 xv = *(const float4*)&xs[k * 16 + q * 4];
                const ulonglong2* wp = (const ulonglong2*)(ws + (c0 + k) * 64 + p * 8);
                ulonglong2 wa = wp[0];
                ulonglong2 wb = wp[1];
                u64 xp[4] = {pack2(xv.x), pack2(xv.y), pack2(xv.z), pack2(xv.w)};
#pragma unroll
                for (int d = 0; d < 4; d++) {
                    ffma2(acc[d][0], xp[d], wa.x);
                    ffma2(acc[d][1], xp[d], wa.y);
                    ffma2(acc[d][2], xp[d], wb.x);
                    ffma2(acc[d][3], xp[d], wb.y);
                }
            }
        }

#pragma unroll
        for (int d = 0; d < 4; d++) {
            int nn = t * 16 + q * 4 + d;
            float* dst = out + (size_t)nn * NOUT_TOTAL + yoff + p * 8;
#pragma unroll
            for (int g = 0; g < 2; g++) {
                float2 a = unpack2(acc[d][2 * g]);
                float2 c = unpack2(acc[d][2 * g + 1]);
                float4 v = make_float4(a.x, a.y, c.x, c.y);
                if (DO_SILU) {
                    v.x = silu(v.x); v.y = silu(v.y);
                    v.z = silu(v.z); v.w = silu(v.w);
                }
                if (DO_RES) {
                    float4 r = *(const float4*)(dst + g * 4);
                    v.x += r.x; v.y += r.y; v.z += r.z; v.w += r.w;
                }
                *(float4*)(dst + g * 4) = v;
            }
        }
    }
}

// ---------------------------------------------------------------------------
// Edge kernel (sorted edges), staging stride XSTR=82
// ---------------------------------------------------------------------------
#define SM_IDX  0
#define SM_B2S  128
#define SM_X2   192
#define SM_B2P  (192 + 128 * XSTR)
#define SM_EDGE_FLOATS (SM_B2P + 8 * 4 * 32 * 4)
#define SM_EDGE_BYTES  (SM_EDGE_FLOATS * 4)

__global__ void __launch_bounds__(256, 3)
edge_kernel2(const int* __restrict__ srow, const int* __restrict__ scol,
             const float* __restrict__ P,
             const float* __restrict__ W2, const float* __restrict__ b2)
{
    extern __shared__ float sm[];
    int*   idxs = (int*)sm;
    float* b2s  = sm + SM_B2S;
    float* X2   = sm + SM_X2;
    float* B2p  = sm + SM_B2P;

    const int tid  = threadIdx.x;
    const int warp = tid >> 5, lane = tid & 31;
    const int g    = lane >> 2, tig = lane & 3;

    for (int i = tid; i < 8 * 4 * 32; i += 256) {
        int s  = i >> 7;
        int gp = (i >> 5) & 3;
        int ln = i & 31;
        int gg = ln >> 2, tt = ln & 3;
        int k0 = s * 8;
        int nA = gp * 16 + (gg >> 1) * 4 + (gg & 1);
        int nB = nA + 2;
        float4 v;
        v.x = tf32f(W2[(k0 + tt)     * 64 + nA]);
        v.y = tf32f(W2[(k0 + tt + 4) * 64 + nA]);
        v.z = tf32f(W2[(k0 + tt)     * 64 + nB]);
        v.w = tf32f(W2[(k0 + tt + 4) * 64 + nB]);
        *(float4*)&B2p[i * 4] = v;
    }
    if (tid < 64) b2s[tid] = b2[tid];
    __syncthreads();

    const float* xlo = X2 + (warp * 16 + g) * XSTR + tig * 2;
    const float* xhi = xlo + 8 * XSTR;

    for (int t = blockIdx.x; t < E_EDGES / ET; t += gridDim.x) {
        {
            int e = tid >> 1, half = tid & 1;
            int row  = srow[t * ET + e];
            int coln = scol[t * ET + e];
            if (half == 0) idxs[e] = row;
            const float4* pa = (const float4*)(P + (size_t)row  * HID + half * 32);
            const float4* pb = (const float4*)(P + (size_t)coln * HID + 64 + half * 32);
            float va[32];
#pragma unroll
            for (int i = 0; i < 8; i++) {
                float4 x = pa[i];
                float4 y = pb[i];
                va[i * 4 + 0] = tf32f(silu(x.x + y.x));
                va[i * 4 + 1] = tf32f(silu(x.y + y.y));
                va[i * 4 + 2] = tf32f(silu(x.z + y.z));
                va[i * 4 + 3] = tf32f(silu(x.w + y.w));
            }
            float* xr = X2 + e * XSTR;
#pragma unroll
            for (int b = 0; b < 4; b++)
#pragma unroll
                for (int j = 0; j < 4; j++) {
                    float2 v = make_float2(va[(b * 2) * 4 + j], va[(b * 2 + 1) * 4 + j]);
                    *(float2*)&xr[(half * 4 + b) * 8 + j * 2] = v;
                }
        }
        __syncthreads();

        float acc[8][4];
#pragma unroll
        for (int a = 0; a < 8; a++)
#pragma unroll
            for (int c = 0; c < 4; c++) acc[a][c] = 0.f;

#pragma unroll
        for (int s = 0; s < 8; s++) {
            float2 alo = *(const float2*)(xlo + s * 8);
            float2 ahi = *(const float2*)(xhi + s * 8);
            u32 a0 = __float_as_uint(alo.x), a1 = __float_as_uint(ahi.x);
            u32 a2 = __float_as_uint(alo.y), a3 = __float_as_uint(ahi.y);
#pragma unroll
            for (int gp = 0; gp < 4; gp++) {
                float4 bv = *(const float4*)&B2p[((s * 4 + gp) * 32 + lane) * 4];
                mma_tf32(acc[gp * 2 + 0], a0, a1, a2, a3,
                         __float_as_uint(bv.x), __float_as_uint(bv.y));
                mma_tf32(acc[gp * 2 + 1], a0, a1, a2, a3,
                         __float_as_uint(bv.z), __float_as_uint(bv.w));
            }
        }

        {
            int nlo = idxs[warp * 16 + g];
            int nhi = idxs[warp * 16 + g + 8];
            float* dlo = g_agg + (size_t)nlo * EH;
            float* dhi = g_agg + (size_t)nhi * EH;
#pragma unroll
            for (int gp = 0; gp < 4; gp++) {
                int c0 = gp * 16 + tig * 4;
                red4(dlo + c0,
                     silu(acc[gp*2][0]   + b2s[c0]),   silu(acc[gp*2][1]   + b2s[c0+1]),
                     silu(acc[gp*2+1][0] + b2s[c0+2]), silu(acc[gp*2+1][1] + b2s[c0+3]));
                red4(dhi + c0,
                     silu(acc[gp*2][2]   + b2s[c0]),   silu(acc[gp*2][3]   + b2s[c0+1]),
                     silu(acc[gp*2+1][2] + b2s[c0+2]), silu(acc[gp*2+1][3] + b2s[c0+3]));
            }
        }
        __syncthreads();
    }
}

// ---------------------------------------------------------------------------
extern "C" void kernel_launch(void* const* d_in, const int* in_sizes, int n_in,
                              void* d_out, int out_size)
{
    const float* h_in  = (const float*)d_in[0];
    const int*   edges = (const int*)d_in[1];
    const float* W_in  = (const float*)d_in[2];
    const float* b_in  = (const float*)d_in[3];
    const float* eW1   = (const float*)d_in[4];
    const float* eb1   = (const float*)d_in[5];
    const float* eW2   = (const float*)d_in[6];
    const float* eb2   = (const float*)d_in[7];
    const float* nW1   = (const float*)d_in[8];
    const float* nb1   = (const float*)d_in[9];
    const float* nW2   = (const float*)d_in[10];
    const float* nb2   = (const float*)d_in[11];
    const float* W_out = (const float*)d_in[12];
    const float* b_out = (const float*)d_in[13];

    float* ph;   cudaGetSymbolAddress((void**)&ph,   g_h);
    float* pag;  cudaGetSymbolAddress((void**)&pag,  g_agg);
    float* pz;   cudaGetSymbolAddress((void**)&pz,   g_z);
    float* pwc;  cudaGetSymbolAddress((void**)&pwc,  g_wcat);
    float* pbc;  cudaGetSymbolAddress((void**)&pbc,  g_bcat);
    int* psrow;  cudaGetSymbolAddress((void**)&psrow, g_srow);
    int* pscol;  cudaGetSymbolAddress((void**)&pscol, g_scol);

    auto smem_g3 = [](int kdim) { return (kdim * 64 + 64 + 8 * 64 * 16) * 4; };
    const int sm_ei  = smem_g3(64);
    const int sm_p   = smem_g3(128);
    const int sm_m128 = (64 + 128 * XSTR + 16 * 4 * 32 * 4) * 4;   // 75008
    const int sm_m192 = (64 + 128 * XSTR + 24 * 4 * 32 * 4) * 4;   // 91392

    cudaFuncSetAttribute(edge_kernel2, cudaFuncAttributeMaxDynamicSharedMemorySize, SM_EDGE_BYTES);
    cudaFuncSetAttribute(node_mma<128, 128, false>,
                         cudaFuncAttributeMaxDynamicSharedMemorySize, sm_m128);
    cudaFuncSetAttribute(node_mma<192, 128, true>,
                         cudaFuncAttributeMaxDynamicSharedMemorySize, sm_m192);
    cudaFuncSetAttribute(node_gemm3<64, 64, 128, false, false>,
                         cudaFuncAttributeMaxDynamicSharedMemorySize, sm_ei);
    cudaFuncSetAttribute(node_gemm3<128, 128, 128, false, true>,
                         cudaFuncAttributeMaxDynamicSharedMemorySize, sm_p);
    cudaFuncSetAttribute(node_gemm3<128, 128, 64, false, false>,
                         cudaFuncAttributeMaxDynamicSharedMemorySize, sm_p);

    const int EB = (E_EDGES + 255) / 256;

    // sort edges by row
    k_zero_deg<<<SCAN_BLOCKS, 256>>>();
    k_hist<<<EB, 256>>>(edges);
    k_scan1<<<SCAN_BLOCKS, 256>>>();
    k_scan2<<<1, 256>>>();
    k_scan3<<<SCAN_BLOCKS, 256>>>();
    k_sort_scatter<<<EB, 256>>>(edges);

    // embedding_in (fp32)
    node_gemm3<64, 64, 128, false, false><<<dim3(148, 2), 256, sm_ei>>>(
        h_in, nullptr, W_in, b_in, ph);

    for (int l = 0; l < L_LAYERS; l++) {
        prep_layer<<<(N_NODES * EH / 4 + 255) / 256, 256>>>(
            eW1 + l * 2 * HID * EH, eb1 + l * EH);
        // P = h @ [W1a|W1b] + [b1|0]  (tf32 mma)
        node_mma<128, 128, false><<<dim3(148, 2), 256, sm_m128>>>(
            ph, nullptr, pwc, pbc, pz);
        edge_kernel2<<<444, 256, SM_EDGE_BYTES>>>(
            psrow, pscol, pz, eW2 + l * EH * EH, eb2 + l * EH);
        // z = silu(concat(h, agg) @ nW1 + nb1)  (tf32 mma)
        node_mma<192, 128, true><<<dim3(148, 2), 256, sm_m192>>>(
            ph, pag, nW1 + l * (HID + EH) * HID, nb1 + l * HID, pz);
        // h = h + (z @ nW2 + nb2)  (fp32, residual anchor)
        node_gemm3<128, 128, 128, false, true><<<dim3(148, 2), 256, sm_p>>>(
            pz, nullptr, nW2 + l * HID * HID, nb2 + l * HID, ph);
    }

    // embedding_out (fp32)
    node_gemm3<128, 128, 64, false, false><<<dim3(148, 1), 256, sm_p>>>(
        ph, nullptr, W_out, b_out, (float*)d_out);
}

// round 8
// speedup vs baseline: 3.9999x; 1.0137x over previous
#include <cuda_runtime.h>
#include <cuda_bf16.h>
#include <cstdint>

// GNN_84421877170708: 4-layer GCL GNN. Round 8:
//  - edge kernel: tile-local segmented scatter (rows sorted -> accumulate
//    runs of equal row in registers, one red4 per run instead of per edge).
//  - everything else as round 7 (tf32 mma for P/na/MLP2; fp32 nb+embeddings).

#define N_NODES 50000
#define E_EDGES 800000
#define IN_NF   64
#define HID     128
#define EH      64
#define OUT_NF  64
#define L_LAYERS 4
#define ET      128
#define XSTR    82
#define SCAN_BLOCKS ((N_NODES + 255) / 256)

__device__ float g_h[N_NODES * HID];
__device__ float g_agg[N_NODES * EH];
__device__ float g_z[N_NODES * HID];
__device__ float g_wcat[HID * HID];
__device__ float g_bcat[HID];

__device__ int g_deg[N_NODES];
__device__ int g_base[N_NODES];
__device__ int g_cursor[N_NODES];
__device__ int g_bsums[256];
__device__ int g_srow[E_EDGES];
__device__ int g_scol[E_EDGES];

using u64 = unsigned long long;
using u32 = unsigned int;

__device__ __forceinline__ float silu(float v) {
    float h = 0.5f * v, t;
    asm("tanh.approx.f32 %0, %1;" : "=f"(t) : "f"(h));
    return fmaf(h, t, h);
}
__device__ __forceinline__ u32 f2tf32(float f) {
    u32 r; asm("cvt.rna.tf32.f32 %0, %1;" : "=r"(r) : "f"(f)); return r;
}
__device__ __forceinline__ float tf32f(float f) {
    return __uint_as_float(f2tf32(f));
}
__device__ __forceinline__ void mma_tf32(float* c, u32 a0, u32 a1, u32 a2, u32 a3,
                                         u32 b0, u32 b1) {
    asm volatile(
        "mma.sync.aligned.m16n8k8.row.col.f32.tf32.tf32.f32 "
        "{%0,%1,%2,%3}, {%4,%5,%6,%7}, {%8,%9}, {%0,%1,%2,%3};"
        : "+f"(c[0]), "+f"(c[1]), "+f"(c[2]), "+f"(c[3])
        : "r"(a0), "r"(a1), "r"(a2), "r"(a3), "r"(b0), "r"(b1));
}
__device__ __forceinline__ void red4(float* p, float a, float b, float c, float d) {
    asm volatile("red.global.add.v4.f32 [%0], {%1,%2,%3,%4};"
                 :: "l"(p), "f"(a), "f"(b), "f"(c), "f"(d) : "memory");
}
__device__ __forceinline__ void ffma2(u64& acc, u64 x, u64 w) {
    asm("fma.rn.f32x2 %0, %1, %2, %0;" : "+l"(acc) : "l"(x), "l"(w));
}
__device__ __forceinline__ u64 pack2(float x) {
    u64 r; asm("mov.b64 %0, {%1, %1};" : "=l"(r) : "f"(x)); return r;
}
__device__ __forceinline__ u64 packf2(float a, float b) {
    u64 r; asm("mov.b64 %0, {%1, %2};" : "=l"(r) : "f"(a), "f"(b)); return r;
}
__device__ __forceinline__ float2 unpack2(u64 v) {
    float2 r; asm("mov.b64 {%0, %1}, %2;" : "=f"(r.x), "=f"(r.y) : "l"(v)); return r;
}

// ---------------------------------------------------------------------------
// counting sort of edges by row
// ---------------------------------------------------------------------------
__global__ void k_zero_deg() {
    int i = blockIdx.x * 256 + threadIdx.x;
    if (i < N_NODES) { g_deg[i] = 0; g_cursor[i] = 0; }
}
__global__ void k_hist(const int* __restrict__ edges) {
    int e = blockIdx.x * 256 + threadIdx.x;
    if (e < E_EDGES) atomicAdd(&g_deg[edges[e]], 1);
}
__global__ void k_scan1() {
    __shared__ int s[256];
    int i = blockIdx.x * 256 + threadIdx.x;
    int v = (i < N_NODES) ? g_deg[i] : 0;
    s[threadIdx.x] = v;
    __syncthreads();
#pragma unroll
    for (int o = 1; o < 256; o <<= 1) {
        int t = (threadIdx.x >= o) ? s[threadIdx.x - o] : 0;
        __syncthreads();
        s[threadIdx.x] += t;
        __syncthreads();
    }
    if (i < N_NODES) g_base[i] = s[threadIdx.x] - v;
    if (threadIdx.x == 255) g_bsums[blockIdx.x] = s[255];
}
__global__ void k_scan2() {
    __shared__ int s[256];
    int i = threadIdx.x;
    int v = (i < SCAN_BLOCKS) ? g_bsums[i] : 0;
    s[i] = v;
    __syncthreads();
#pragma unroll
    for (int o = 1; o < 256; o <<= 1) {
        int t = (i >= o) ? s[i - o] : 0;
        __syncthreads();
        s[i] += t;
        __syncthreads();
    }
    g_bsums[i] = s[i] - v;
}
__global__ void k_scan3() {
    int i = blockIdx.x * 256 + threadIdx.x;
    if (i < N_NODES) g_base[i] += g_bsums[blockIdx.x];
}
__global__ void k_sort_scatter(const int* __restrict__ edges) {
    int e = blockIdx.x * 256 + threadIdx.x;
    if (e < E_EDGES) {
        int r = edges[e], c = edges[E_EDGES + e];
        int pos = g_base[r] + atomicAdd(&g_cursor[r], 1);
        g_srow[pos] = r;
        g_scol[pos] = c;
    }
}

// ---------------------------------------------------------------------------
__global__ void prep_layer(const float* __restrict__ eW1, const float* __restrict__ b1) {
    int i = blockIdx.x * 256 + threadIdx.x;
    if (i < N_NODES * EH / 4)
        ((float4*)g_agg)[i] = make_float4(0.f, 0.f, 0.f, 0.f);
    if (i < HID * HID) {
        int k = i >> 7, j = i & 127;
        g_wcat[i] = (j < 64) ? eW1[k * 64 + j] : eW1[(k + 128) * 64 + (j - 64)];
    }
    if (i < HID) g_bcat[i] = (i < 64) ? b1[i] : 0.f;
}

// ---------------------------------------------------------------------------
// node_mma (tf32): out[:, yoff:+64] = act(concat(in1,in2) @ W[:, yoff:+64] + b)
// ---------------------------------------------------------------------------
template<int KDIM, int W1IN, bool DO_SILU>
__global__ void __launch_bounds__(256, 2) node_mma(
    const float* __restrict__ in1, const float* __restrict__ in2,
    const float* __restrict__ W, const float* __restrict__ b,
    float* __restrict__ out)
{
    constexpr int NSTEP = KDIM / 8;
    extern __shared__ float sm[];
    float* bs = sm;
    float* X  = sm + 64;
    float* Bp = X + 128 * XSTR;

    const int tid  = threadIdx.x;
    const int warp = tid >> 5, lane = tid & 31;
    const int g    = lane >> 2, tig = lane & 3;
    const int yoff = blockIdx.y * 64;

    for (int i = tid; i < NSTEP * 4 * 32; i += 256) {
        int s  = i >> 7;
        int gp = (i >> 5) & 3;
        int ln = i & 31;
        int gg = ln >> 2, tt = ln & 3;
        int k0 = s * 8;
        int nA = yoff + gp * 16 + (gg >> 1) * 4 + (gg & 1);
        int nB = nA + 2;
        float4 v;
        v.x = tf32f(W[(size_t)(k0 + tt)     * HID + nA]);
        v.y = tf32f(W[(size_t)(k0 + tt + 4) * HID + nA]);
        v.z = tf32f(W[(size_t)(k0 + tt)     * HID + nB]);
        v.w = tf32f(W[(size_t)(k0 + tt + 4) * HID + nB]);
        *(float4*)&Bp[i * 4] = v;
    }
    if (tid < 64) bs[tid] = b[yoff + tid];

    const float* xlo = X + (warp * 16 + g) * XSTR + tig * 2;
    const float* xhi = xlo + 8 * XSTR;
    const int e  = tid >> 1;
    const int hf = tid & 1;

    const int NTILES = (N_NODES + 127) / 128;
    for (int t = blockIdx.x; t < NTILES; t += gridDim.x) {
        const int tb = t * 128;
        int node = tb + e;
        if (node >= N_NODES) node = 0;

        float acc[8][4];
#pragma unroll
        for (int a = 0; a < 8; a++)
#pragma unroll
            for (int c = 0; c < 4; c++) acc[a][c] = 0.f;

#pragma unroll
        for (int c0 = 0; c0 < KDIM; c0 += 64) {
            __syncthreads();
            {
                const int kb = c0 + hf * 32;
                const float4* src;
                if (KDIM == W1IN || kb < W1IN)
                    src = (const float4*)(in1 + (size_t)node * W1IN + kb);
                else
                    src = (const float4*)(in2 + (size_t)node * (KDIM - W1IN) + (kb - W1IN));
                float va[32];
#pragma unroll
                for (int i = 0; i < 8; i++) {
                    float4 v = src[i];
                    va[i * 4 + 0] = tf32f(v.x);
                    va[i * 4 + 1] = tf32f(v.y);
                    va[i * 4 + 2] = tf32f(v.z);
                    va[i * 4 + 3] = tf32f(v.w);
                }
                float* xr = X + e * XSTR;
#pragma unroll
                for (int bb = 0; bb < 4; bb++)
#pragma unroll
                    for (int j = 0; j < 4; j++) {
                        float2 v = make_float2(va[(bb * 2) * 4 + j], va[(bb * 2 + 1) * 4 + j]);
                        *(float2*)&xr[(hf * 4 + bb) * 8 + j * 2] = v;
                    }
            }
            __syncthreads();

#pragma unroll
            for (int s8 = 0; s8 < 8; s8++) {
                const int s = (c0 >> 3) + s8;
                float2 alo = *(const float2*)(xlo + s8 * 8);
                float2 ahi = *(const float2*)(xhi + s8 * 8);
                u32 a0 = __float_as_uint(alo.x), a1 = __float_as_uint(ahi.x);
                u32 a2 = __float_as_uint(alo.y), a3 = __float_as_uint(ahi.y);
#pragma unroll
                for (int gp = 0; gp < 4; gp++) {
                    float4 bv = *(const float4*)&Bp[((s * 4 + gp) * 32 + lane) * 4];
                    mma_tf32(acc[gp * 2 + 0], a0, a1, a2, a3,
                             __float_as_uint(bv.x), __float_as_uint(bv.y));
                    mma_tf32(acc[gp * 2 + 1], a0, a1, a2, a3,
                             __float_as_uint(bv.z), __float_as_uint(bv.w));
                }
            }
        }

        {
            int r0 = tb + warp * 16 + g;
            int r1 = r0 + 8;
#pragma unroll
            for (int gp = 0; gp < 4; gp++) {
                int c0 = gp * 16 + tig * 4;
                float4 v0 = make_float4(acc[gp*2][0]   + bs[c0],
                                        acc[gp*2][1]   + bs[c0+1],
                                        acc[gp*2+1][0] + bs[c0+2],
                                        acc[gp*2+1][1] + bs[c0+3]);
                float4 v1 = make_float4(acc[gp*2][2]   + bs[c0],
                                        acc[gp*2][3]   + bs[c0+1],
                                        acc[gp*2+1][2] + bs[c0+2],
                                        acc[gp*2+1][3] + bs[c0+3]);
                if (DO_SILU) {
                    v0.x = silu(v0.x); v0.y = silu(v0.y); v0.z = silu(v0.z); v0.w = silu(v0.w);
                    v1.x = silu(v1.x); v1.y = silu(v1.y); v1.z = silu(v1.z); v1.w = silu(v1.w);
                }
                if (r0 < N_NODES) *(float4*)(out + (size_t)r0 * HID + yoff + c0) = v0;
                if (r1 < N_NODES) *(float4*)(out + (size_t)r1 * HID + yoff + c0) = v1;
            }
        }
    }
}

// ---------------------------------------------------------------------------
// node_gemm3 (fp32, residual nb + embeddings)
// ---------------------------------------------------------------------------
template<int KDIM, int W1IN, int NOUT_TOTAL, bool DO_SILU, bool DO_RES>
__global__ void __launch_bounds__(256, 2) node_gemm3(
    const float* __restrict__ in1, const float* __restrict__ in2,
    const float* __restrict__ W, const float* __restrict__ b,
    float* __restrict__ out)
{
    extern __shared__ float fsmem[];
    float* ws = fsmem;
    float* bs = ws + KDIM * 64;
    float* stg = bs + 64;

    const int tid  = threadIdx.x;
    const int warp = tid >> 5;
    const int lane = tid & 31;
    const int yoff = blockIdx.y * 64;

    for (int i = tid * 4; i < KDIM * 64; i += 1024) {
        int k = i >> 6, j = i & 63;
        *(float4*)&ws[i] = *(const float4*)(W + (size_t)k * NOUT_TOTAL + yoff + j);
    }
    if (tid < 64) bs[tid] = b[yoff + tid];
    __syncthreads();

    float* xs = stg + warp * (64 * 16);
    const int p    = lane >> 2;
    const int q    = lane & 3;
    const int m    = lane >> 1;
    const int half = lane & 1;

    u64 biasr[4];
#pragma unroll
    for (int g = 0; g < 4; g++)
        biasr[g] = packf2(bs[p * 8 + 2 * g], bs[p * 8 + 2 * g + 1]);

    const int gw     = blockIdx.x * 8 + warp;
    const int nwarps = gridDim.x * 8;
    const int ntiles = N_NODES / 16;

    for (int t = gw; t < ntiles; t += nwarps) {
        const int node = t * 16 + m;
        const float* s1 = in1 + (size_t)node * W1IN;
        const float* s2 = (KDIM > W1IN) ? in2 + (size_t)node * (KDIM - W1IN) : nullptr;

        u64 acc[4][4];
#pragma unroll
        for (int d = 0; d < 4; d++)
#pragma unroll
            for (int g = 0; g < 4; g++) acc[d][g] = biasr[g];

#pragma unroll
        for (int c0 = 0; c0 < KDIM; c0 += 64) {
            __syncwarp();
#pragma unroll
            for (int i = 0; i < 8; i++) {
                int kk = c0 + half * 32 + i * 4;
                float4 v;
                if (KDIM == W1IN || kk < W1IN) v = *(const float4*)(s1 + kk);
                else                           v = *(const float4*)(s2 + (kk - W1IN));
                int kl = kk - c0;
                xs[(kl + 0) * 16 + m] = v.x;
                xs[(kl + 1) * 16 + m] = v.y;
                xs[(kl + 2) * 16 + m] = v.z;
                xs[(kl + 3) * 16 + m] = v.w;
            }
            __syncwarp();

#pragma unroll 4
            for (int k = 0; k < 64; k++) {
                float4 xv = *(const float4*)&xs[k * 16 + q * 4];
                const ulonglong2* wp = (const ulonglong2*)(ws + (c0 + k) * 64 + p * 8);
                ulonglong2 wa = wp[0];
                ulonglong2 wb = wp[1];
                u64 xp[4] = {pack2(xv.x), pack2(xv.y), pack2(xv.z), pack2(xv.w)};
#pragma unroll
                for (int d = 0; d < 4; d++) {
                    ffma2(acc[d][0], xp[d], wa.x);
                    ffma2(acc[d][1], xp[d], wa.y);
                    ffma2(acc[d][2], xp[d], wb.x);
                    ffma2(acc[d][3], xp[d], wb.y);
                }
            }
        }

#pragma unroll
        for (int d = 0; d < 4; d++) {
            int nn = t * 16 + q * 4 + d;
            float* dst = out + (size_t)nn * NOUT_TOTAL + yoff + p * 8;
#pragma unroll
            for (int g = 0; g < 2; g++) {
                float2 a = unpack2(acc[d][2 * g]);
                float2 c = unpack2(acc[d][2 * g + 1]);
                float4 v = make_float4(a.x, a.y, c.x, c.y);
                if (DO_SILU) {
                    v.x = silu(v.x); v.y = silu(v.y);
                    v.z = silu(v.z); v.w = silu(v.w);
                }
                if (DO_RES) {
                    float4 r = *(const float4*)(dst + g * 4);
                    v.x += r.x; v.y += r.y; v.z += r.z; v.w += r.w;
                }
                *(float4*)(dst + g * 4) = v;
            }
        }
    }
}

// ---------------------------------------------------------------------------
// Edge kernel: sorted edges; gather+silu -> tf32 mma MLP2 ->
// tile-local segmented reduction -> red4 per run.
// ---------------------------------------------------------------------------
#define SM_IDX  0
#define SM_B2S  128
#define SM_X2   192
#define SM_B2P  (192 + 128 * XSTR)
#define SM_EDGE_FLOATS (SM_B2P + 8 * 4 * 32 * 4)
#define SM_EDGE_BYTES  (SM_EDGE_FLOATS * 4)

__global__ void __launch_bounds__(256, 3)
edge_kernel2(const int* __restrict__ srow, const int* __restrict__ scol,
             const float* __restrict__ P,
             const float* __restrict__ W2, const float* __restrict__ b2)
{
    extern __shared__ float sm[];
    int*   idxs = (int*)sm;
    float* b2s  = sm + SM_B2S;
    float* X2   = sm + SM_X2;
    float* B2p  = sm + SM_B2P;

    const int tid  = threadIdx.x;
    const int warp = tid >> 5, lane = tid & 31;
    const int g    = lane >> 2, tig = lane & 3;

    for (int i = tid; i < 8 * 4 * 32; i += 256) {
        int s  = i >> 7;
        int gp = (i >> 5) & 3;
        int ln = i & 31;
        int gg = ln >> 2, tt = ln & 3;
        int k0 = s * 8;
        int nA = gp * 16 + (gg >> 1) * 4 + (gg & 1);
        int nB = nA + 2;
        float4 v;
        v.x = tf32f(W2[(k0 + tt)     * 64 + nA]);
        v.y = tf32f(W2[(k0 + tt + 4) * 64 + nA]);
        v.z = tf32f(W2[(k0 + tt)     * 64 + nB]);
        v.w = tf32f(W2[(k0 + tt + 4) * 64 + nB]);
        *(float4*)&B2p[i * 4] = v;
    }
    if (tid < 64) b2s[tid] = b2[tid];
    __syncthreads();

    const float* xlo = X2 + (warp * 16 + g) * XSTR + tig * 2;
    const float* xhi = xlo + 8 * XSTR;
    const int e_lo = warp * 16 + g;
    const int e_hi = e_lo + 8;
    const int qd = tid & 15;        // column quad 0..15 (reduction pass)
    const int sp = tid >> 4;        // edge strip 0..15 (8 edges each)

    for (int t = blockIdx.x; t < E_EDGES / ET; t += gridDim.x) {
        // ---- gather + silu -> X2 (frag-interleaved tf32) ----
        {
            int e = tid >> 1, half = tid & 1;
            int row  = srow[t * ET + e];
            int coln = scol[t * ET + e];
            if (half == 0) idxs[e] = row;
            const float4* pa = (const float4*)(P + (size_t)row  * HID + half * 32);
            const float4* pb = (const float4*)(P + (size_t)coln * HID + 64 + half * 32);
            float va[32];
#pragma unroll
            for (int i = 0; i < 8; i++) {
                float4 x = pa[i];
                float4 y = pb[i];
                va[i * 4 + 0] = tf32f(silu(x.x + y.x));
                va[i * 4 + 1] = tf32f(silu(x.y + y.y));
                va[i * 4 + 2] = tf32f(silu(x.z + y.z));
                va[i * 4 + 3] = tf32f(silu(x.w + y.w));
            }
            float* xr = X2 + e * XSTR;
#pragma unroll
            for (int b = 0; b < 4; b++)
#pragma unroll
                for (int j = 0; j < 4; j++) {
                    float2 v = make_float2(va[(b * 2) * 4 + j], va[(b * 2 + 1) * 4 + j]);
                    *(float2*)&xr[(half * 4 + b) * 8 + j * 2] = v;
                }
        }
        __syncthreads();

        // ---- MLP2 MMA ----
        float acc[8][4];
#pragma unroll
        for (int a = 0; a < 8; a++)
#pragma unroll
            for (int c = 0; c < 4; c++) acc[a][c] = 0.f;

#pragma unroll
        for (int s = 0; s < 8; s++) {
            float2 alo = *(const float2*)(xlo + s * 8);
            float2 ahi = *(const float2*)(xhi + s * 8);
            u32 a0 = __float_as_uint(alo.x), a1 = __float_as_uint(ahi.x);
            u32 a2 = __float_as_uint(alo.y), a3 = __float_as_uint(ahi.y);
#pragma unroll
            for (int gp = 0; gp < 4; gp++) {
                float4 bv = *(const float4*)&B2p[((s * 4 + gp) * 32 + lane) * 4];
                mma_tf32(acc[gp * 2 + 0], a0, a1, a2, a3,
                         __float_as_uint(bv.x), __float_as_uint(bv.y));
                mma_tf32(acc[gp * 2 + 1], a0, a1, a2, a3,
                         __float_as_uint(bv.z), __float_as_uint(bv.w));
            }
        }
        __syncthreads();   // all MMA reads of X2 done; safe to overwrite

        // ---- write silu(D2 + b2) back into X2 as R[e][0..63] (stride XSTR) ----
        {
            float* rlo = X2 + e_lo * XSTR;
            float* rhi = X2 + e_hi * XSTR;
#pragma unroll
            for (int gp = 0; gp < 4; gp++) {
                int c0 = gp * 16 + tig * 4;
                *(float2*)&rlo[c0]     = make_float2(silu(acc[gp*2][0]   + b2s[c0]),
                                                     silu(acc[gp*2][1]   + b2s[c0+1]));
                *(float2*)&rlo[c0 + 2] = make_float2(silu(acc[gp*2+1][0] + b2s[c0+2]),
                                                     silu(acc[gp*2+1][1] + b2s[c0+3]));
                *(float2*)&rhi[c0]     = make_float2(silu(acc[gp*2][2]   + b2s[c0]),
                                                     silu(acc[gp*2][3]   + b2s[c0+1]));
                *(float2*)&rhi[c0 + 2] = make_float2(silu(acc[gp*2+1][2] + b2s[c0+2]),
                                                     silu(acc[gp*2+1][3] + b2s[c0+3]));
            }
        }
        __syncthreads();

        // ---- segmented reduction: thread (qd, sp) walks 8 edges for 4 cols ----
        {
            int e0 = sp * 8;
            int cur = idxs[e0];
            const float* r = X2 + e0 * XSTR + qd * 4;
            float2 a01 = *(const float2*)(r);
            float2 a23 = *(const float2*)(r + 2);
            float s0 = a01.x, s1 = a01.y, s2 = a23.x, s3 = a23.y;
#pragma unroll
            for (int j = 1; j < 8; j++) {
                int rw = idxs[e0 + j];
                const float* rr = X2 + (e0 + j) * XSTR + qd * 4;
                float2 b01 = *(const float2*)(rr);
                float2 b23 = *(const float2*)(rr + 2);
                if (rw != cur) {
                    red4(g_agg + (size_t)cur * EH + qd * 4, s0, s1, s2, s3);
                    cur = rw;
                    s0 = b01.x; s1 = b01.y; s2 = b23.x; s3 = b23.y;
                } else {
                    s0 += b01.x; s1 += b01.y; s2 += b23.x; s3 += b23.y;
                }
            }
            red4(g_agg + (size_t)cur * EH + qd * 4, s0, s1, s2, s3);
        }
        __syncthreads();
    }
}

// ---------------------------------------------------------------------------
extern "C" void kernel_launch(void* const* d_in, const int* in_sizes, int n_in,
                              void* d_out, int out_size)
{
    const float* h_in  = (const float*)d_in[0];
    const int*   edges = (const int*)d_in[1];
    const float* W_in  = (const float*)d_in[2];
    const float* b_in  = (const float*)d_in[3];
    const float* eW1   = (const float*)d_in[4];
    const float* eb1   = (const float*)d_in[5];
    const float* eW2   = (const float*)d_in[6];
    const float* eb2   = (const float*)d_in[7];
    const float* nW1   = (const float*)d_in[8];
    const float* nb1   = (const float*)d_in[9];
    const float* nW2   = (const float*)d_in[10];
    const float* nb2   = (const float*)d_in[11];
    const float* W_out = (const float*)d_in[12];
    const float* b_out = (const float*)d_in[13];

    float* ph;   cudaGetSymbolAddress((void**)&ph,   g_h);
    float* pag;  cudaGetSymbolAddress((void**)&pag,  g_agg);
    float* pz;   cudaGetSymbolAddress((void**)&pz,   g_z);
    float* pwc;  cudaGetSymbolAddress((void**)&pwc,  g_wcat);
    float* pbc;  cudaGetSymbolAddress((void**)&pbc,  g_bcat);
    int* psrow;  cudaGetSymbolAddress((void**)&psrow, g_srow);
    int* pscol;  cudaGetSymbolAddress((void**)&pscol, g_scol);

    auto smem_g3 = [](int kdim) { return (kdim * 64 + 64 + 8 * 64 * 16) * 4; };
    const int sm_ei  = smem_g3(64);
    const int sm_p   = smem_g3(128);
    const int sm_m128 = (64 + 128 * XSTR + 16 * 4 * 32 * 4) * 4;
    const int sm_m192 = (64 + 128 * XSTR + 24 * 4 * 32 * 4) * 4;

    cudaFuncSetAttribute(edge_kernel2, cudaFuncAttributeMaxDynamicSharedMemorySize, SM_EDGE_BYTES);
    cudaFuncSetAttribute(node_mma<128, 128, false>,
                         cudaFuncAttributeMaxDynamicSharedMemorySize, sm_m128);
    cudaFuncSetAttribute(node_mma<192, 128, true>,
                         cudaFuncAttributeMaxDynamicSharedMemorySize, sm_m192);
    cudaFuncSetAttribute(node_gemm3<64, 64, 128, false, false>,
                         cudaFuncAttributeMaxDynamicSharedMemorySize, sm_ei);
    cudaFuncSetAttribute(node_gemm3<128, 128, 128, false, true>,
                         cudaFuncAttributeMaxDynamicSharedMemorySize, sm_p);
    cudaFuncSetAttribute(node_gemm3<128, 128, 64, false, false>,
                         cudaFuncAttributeMaxDynamicSharedMemorySize, sm_p);

    const int EB = (E_EDGES + 255) / 256;

    k_zero_deg<<<SCAN_BLOCKS, 256>>>();
    k_hist<<<EB, 256>>>(edges);
    k_scan1<<<SCAN_BLOCKS, 256>>>();
    k_scan2<<<1, 256>>>();
    k_scan3<<<SCAN_BLOCKS, 256>>>();
    k_sort_scatter<<<EB, 256>>>(edges);

    node_gemm3<64, 64, 128, false, false><<<dim3(148, 2), 256, sm_ei>>>(
        h_in, nullptr, W_in, b_in, ph);

    for (int l = 0; l < L_LAYERS; l++) {
        prep_layer<<<(N_NODES * EH / 4 + 255) / 256, 256>>>(
            eW1 + l * 2 * HID * EH, eb1 + l * EH);
        node_mma<128, 128, false><<<dim3(148, 2), 256, sm_m128>>>(
            ph, nullptr, pwc, pbc, pz);
        edge_kernel2<<<444, 256, SM_EDGE_BYTES>>>(
            psrow, pscol, pz, eW2 + l * EH * EH, eb2 + l * EH);
        node_mma<192, 128, true><<<dim3(148, 2), 256, sm_m192>>>(
            ph, pag, nW1 + l * (HID + EH) * HID, nb1 + l * HID, pz);
        node_gemm3<128, 128, 128, false, true><<<dim3(148, 2), 256, sm_p>>>(
            pz, nullptr, nW2 + l * HID * HID, nb2 + l * HID, ph);
    }

    node_gemm3<128, 128, 64, false, false><<<dim3(148, 1), 256, sm_p>>>(
        ph, nullptr, W_out, b_out, (float*)d_out);
}

// round 9
// speedup vs baseline: 4.0144x; 1.0036x over previous
#include <cuda_runtime.h>
#include <cuda_bf16.h>
#include <cstdint>

// GNN_84421877170708: 4-layer GCL GNN. Round 8:
//  - edge kernel: tile-local segmented scatter (rows sorted -> accumulate
//    runs of equal row in registers, one red4 per run instead of per edge).
//  - everything else as round 7 (tf32 mma for P/na/MLP2; fp32 nb+embeddings).

#define N_NODES 50000
#define E_EDGES 800000
#define IN_NF   64
#define HID     128
#define EH      64
#define OUT_NF  64
#define L_LAYERS 4
#define ET      128
#define XSTR    82
#define SCAN_BLOCKS ((N_NODES + 255) / 256)

__device__ float g_h[N_NODES * HID];
__device__ float g_agg[N_NODES * EH];
__device__ float g_z[N_NODES * HID];
__device__ float g_wcat[HID * HID];
__device__ float g_bcat[HID];

__device__ int g_deg[N_NODES];
__device__ int g_base[N_NODES];
__device__ int g_cursor[N_NODES];
__device__ int g_bsums[256];
__device__ int g_srow[E_EDGES];
__device__ int g_scol[E_EDGES];

using u64 = unsigned long long;
using u32 = unsigned int;

__device__ __forceinline__ float silu(float v) {
    float h = 0.5f * v, t;
    asm("tanh.approx.f32 %0, %1;" : "=f"(t) : "f"(h));
    return fmaf(h, t, h);
}
__device__ __forceinline__ u32 f2tf32(float f) {
    u32 r; asm("cvt.rna.tf32.f32 %0, %1;" : "=r"(r) : "f"(f)); return r;
}
__device__ __forceinline__ float tf32f(float f) {
    return __uint_as_float(f2tf32(f));
}
__device__ __forceinline__ void mma_tf32(float* c, u32 a0, u32 a1, u32 a2, u32 a3,
                                         u32 b0, u32 b1) {
    asm volatile(
        "mma.sync.aligned.m16n8k8.row.col.f32.tf32.tf32.f32 "
        "{%0,%1,%2,%3}, {%4,%5,%6,%7}, {%8,%9}, {%0,%1,%2,%3};"
        : "+f"(c[0]), "+f"(c[1]), "+f"(c[2]), "+f"(c[3])
        : "r"(a0), "r"(a1), "r"(a2), "r"(a3), "r"(b0), "r"(b1));
}
__device__ __forceinline__ void red4(float* p, float a, float b, float c, float d) {
    asm volatile("red.global.add.v4.f32 [%0], {%1,%2,%3,%4};"
                 :: "l"(p), "f"(a), "f"(b), "f"(c), "f"(d) : "memory");
}
__device__ __forceinline__ void ffma2(u64& acc, u64 x, u64 w) {
    asm("fma.rn.f32x2 %0, %1, %2, %0;" : "+l"(acc) : "l"(x), "l"(w));
}
__device__ __forceinline__ u64 pack2(float x) {
    u64 r; asm("mov.b64 %0, {%1, %1};" : "=l"(r) : "f"(x)); return r;
}
__device__ __forceinline__ u64 packf2(float a, float b) {
    u64 r; asm("mov.b64 %0, {%1, %2};" : "=l"(r) : "f"(a), "f"(b)); return r;
}
__device__ __forceinline__ float2 unpack2(u64 v) {
    float2 r; asm("mov.b64 {%0, %1}, %2;" : "=f"(r.x), "=f"(r.y) : "l"(v)); return r;
}

// ---------------------------------------------------------------------------
// counting sort of edges by row
// ---------------------------------------------------------------------------
__global__ void k_zero_deg() {
    int i = blockIdx.x * 256 + threadIdx.x;
    if (i < N_NODES) { g_deg[i] = 0; g_cursor[i] = 0; }
}
__global__ void k_hist(const int* __restrict__ edges) {
    int e = blockIdx.x * 256 + threadIdx.x;
    if (e < E_EDGES) atomicAdd(&g_deg[edges[e]], 1);
}
__global__ void k_scan1() {
    __shared__ int s[256];
    int i = blockIdx.x * 256 + threadIdx.x;
    int v = (i < N_NODES) ? g_deg[i] : 0;
    s[threadIdx.x] = v;
    __syncthreads();
#pragma unroll
    for (int o = 1; o < 256; o <<= 1) {
        int t = (threadIdx.x >= o) ? s[threadIdx.x - o] : 0;
        __syncthreads();
        s[threadIdx.x] += t;
        __syncthreads();
    }
    if (i < N_NODES) g_base[i] = s[threadIdx.x] - v;
    if (threadIdx.x == 255) g_bsums[blockIdx.x] = s[255];
}
__global__ void k_scan2() {
    __shared__ int s[256];
    int i = threadIdx.x;
    int v = (i < SCAN_BLOCKS) ? g_bsums[i] : 0;
    s[i] = v;
    __syncthreads();
#pragma unroll
    for (int o = 1; o < 256; o <<= 1) {
        int t = (i >= o) ? s[i - o] : 0;
        __syncthreads();
        s[i] += t;
        __syncthreads();
    }
    g_bsums[i] = s[i] - v;
}
__global__ void k_scan3() {
    int i = blockIdx.x * 256 + threadIdx.x;
    if (i < N_NODES) g_base[i] += g_bsums[blockIdx.x];
}
__global__ void k_sort_scatter(const int* __restrict__ edges) {
    int e = blockIdx.x * 256 + threadIdx.x;
    if (e < E_EDGES) {
        int r = edges[e], c = edges[E_EDGES + e];
        int pos = g_base[r] + atomicAdd(&g_cursor[r], 1);
        g_srow[pos] = r;
        g_scol[pos] = c;
    }
}

// ---------------------------------------------------------------------------
__global__ void prep_layer(const float* __restrict__ eW1, const float* __restrict__ b1) {
    int i = blockIdx.x * 256 + threadIdx.x;
    if (i < N_NODES * EH / 4)
        ((float4*)g_agg)[i] = make_float4(0.f, 0.f, 0.f, 0.f);
    if (i < HID * HID) {
        int k = i >> 7, j = i & 127;
        g_wcat[i] = (j < 64) ? eW1[k * 64 + j] : eW1[(k + 128) * 64 + (j - 64)];
    }
    if (i < HID) g_bcat[i] = (i < 64) ? b1[i] : 0.f;
}

// ---------------------------------------------------------------------------
// node_mma (tf32): out[:, yoff:+64] = act(concat(in1,in2) @ W[:, yoff:+64] + b)
// ---------------------------------------------------------------------------
template<int KDIM, int W1IN, bool DO_SILU>
__global__ void __launch_bounds__(256, 2) node_mma(
    const float* __restrict__ in1, const float* __restrict__ in2,
    const float* __restrict__ W, const float* __restrict__ b,
    float* __restrict__ out)
{
    constexpr int NSTEP = KDIM / 8;
    extern __shared__ float sm[];
    float* bs = sm;
    float* X  = sm + 64;
    float* Bp = X + 128 * XSTR;

    const int tid  = threadIdx.x;
    const int warp = tid >> 5, lane = tid & 31;
    const int g    = lane >> 2, tig = lane & 3;
    const int yoff = blockIdx.y * 64;

    for (int i = tid; i < NSTEP * 4 * 32; i += 256) {
        int s  = i >> 7;
        int gp = (i >> 5) & 3;
        int ln = i & 31;
        int gg = ln >> 2, tt = ln & 3;
        int k0 = s * 8;
        int nA = yoff + gp * 16 + (gg >> 1) * 4 + (gg & 1);
        int nB = nA + 2;
        float4 v;
        v.x = tf32f(W[(size_t)(k0 + tt)     * HID + nA]);
        v.y = tf32f(W[(size_t)(k0 + tt + 4) * HID + nA]);
        v.z = tf32f(W[(size_t)(k0 + tt)     * HID + nB]);
        v.w = tf32f(W[(size_t)(k0 + tt + 4) * HID + nB]);
        *(float4*)&Bp[i * 4] = v;
    }
    if (tid < 64) bs[tid] = b[yoff + tid];

    const float* xlo = X + (warp * 16 + g) * XSTR + tig * 2;
    const float* xhi = xlo + 8 * XSTR;
    const int e  = tid >> 1;
    const int hf = tid & 1;

    const int NTILES = (N_NODES + 127) / 128;
    for (int t = blockIdx.x; t < NTILES; t += gridDim.x) {
        const int tb = t * 128;
        int node = tb + e;
        if (node >= N_NODES) node = 0;

        float acc[8][4];
#pragma unroll
        for (int a = 0; a < 8; a++)
#pragma unroll
            for (int c = 0; c < 4; c++) acc[a][c] = 0.f;

#pragma unroll
        for (int c0 = 0; c0 < KDIM; c0 += 64) {
            __syncthreads();
            {
                const int kb = c0 + hf * 32;
                const float4* src;
                if (KDIM == W1IN || kb < W1IN)
                    src = (const float4*)(in1 + (size_t)node * W1IN + kb);
                else
                    src = (const float4*)(in2 + (size_t)node * (KDIM - W1IN) + (kb - W1IN));
                float va[32];
#pragma unroll
                for (int i = 0; i < 8; i++) {
                    float4 v = src[i];
                    va[i * 4 + 0] = tf32f(v.x);
                    va[i * 4 + 1] = tf32f(v.y);
                    va[i * 4 + 2] = tf32f(v.z);
                    va[i * 4 + 3] = tf32f(v.w);
                }
                float* xr = X + e * XSTR;
#pragma unroll
                for (int bb = 0; bb < 4; bb++)
#pragma unroll
                    for (int j = 0; j < 4; j++) {
                        float2 v = make_float2(va[(bb * 2) * 4 + j], va[(bb * 2 + 1) * 4 + j]);
                        *(float2*)&xr[(hf * 4 + bb) * 8 + j * 2] = v;
                    }
            }
            __syncthreads();

#pragma unroll
            for (int s8 = 0; s8 < 8; s8++) {
                const int s = (c0 >> 3) + s8;
                float2 alo = *(const float2*)(xlo + s8 * 8);
                float2 ahi = *(const float2*)(xhi + s8 * 8);
                u32 a0 = __float_as_uint(alo.x), a1 = __float_as_uint(ahi.x);
                u32 a2 = __float_as_uint(alo.y), a3 = __float_as_uint(ahi.y);
#pragma unroll
                for (int gp = 0; gp < 4; gp++) {
                    float4 bv = *(const float4*)&Bp[((s * 4 + gp) * 32 + lane) * 4];
                    mma_tf32(acc[gp * 2 + 0], a0, a1, a2, a3,
                             __float_as_uint(bv.x), __float_as_uint(bv.y));
                    mma_tf32(acc[gp * 2 + 1], a0, a1, a2, a3,
                             __float_as_uint(bv.z), __float_as_uint(bv.w));
                }
            }
        }

        {
            int r0 = tb + warp * 16 + g;
            int r1 = r0 + 8;
#pragma unroll
            for (int gp = 0; gp < 4; gp++) {
                int c0 = gp * 16 + tig * 4;
                float4 v0 = make_float4(acc[gp*2][0]   + bs[c0],
                                        acc[gp*2][1]   + bs[c0+1],
                                        acc[gp*2+1][0] + bs[c0+2],
                                        acc[gp*2+1][1] + bs[c0+3]);
                float4 v1 = make_float4(acc[gp*2][2]   + bs[c0],
                                        acc[gp*2][3]   + bs[c0+1],
                                        acc[gp*2+1][2] + bs[c0+2],
                                        acc[gp*2+1][3] + bs[c0+3]);
                if (DO_SILU) {
                    v0.x = silu(v0.x); v0.y = silu(v0.y); v0.z = silu(v0.z); v0.w = silu(v0.w);
                    v1.x = silu(v1.x); v1.y = silu(v1.y); v1.z = silu(v1.z); v1.w = silu(v1.w);
                }
                if (r0 < N_NODES) *(float4*)(out + (size_t)r0 * HID + yoff + c0) = v0;
                if (r1 < N_NODES) *(float4*)(out + (size_t)r1 * HID + yoff + c0) = v1;
            }
        }
    }
}

// ---------------------------------------------------------------------------
// node_gemm3 (fp32, residual nb + embeddings)
// ---------------------------------------------------------------------------
template<int KDIM, int W1IN, int NOUT_TOTAL, bool DO_SILU, bool DO_RES>
__global__ void __launch_bounds__(256, 2) node_gemm3(
    const float* __restrict__ in1, const float* __restrict__ in2,
    const float* __restrict__ W, const float* __restrict__ b,
    float* __restrict__ out)
{
    extern __shared__ float fsmem[];
    float* ws = fsmem;
    float* bs = ws + KDIM * 64;
    float* stg = bs + 64;

    const int tid  = threadIdx.x;
    const int warp = tid >> 5;
    const int lane = tid & 31;
    const int yoff = blockIdx.y * 64;

    for (int i = tid * 4; i < KDIM * 64; i += 1024) {
        int k = i >> 6, j = i & 63;
        *(float4*)&ws[i] = *(const float4*)(W + (size_t)k * NOUT_TOTAL + yoff + j);
    }
    if (tid < 64) bs[tid] = b[yoff + tid];
    __syncthreads();

    float* xs = stg + warp * (64 * 16);
    const int p    = lane >> 2;
    const int q    = lane & 3;
    const int m    = lane >> 1;
    const int half = lane & 1;

    u64 biasr[4];
#pragma unroll
    for (int g = 0; g < 4; g++)
        biasr[g] = packf2(bs[p * 8 + 2 * g], bs[p * 8 + 2 * g + 1]);

    const int gw     = blockIdx.x * 8 + warp;
    const int nwarps = gridDim.x * 8;
    const int ntiles = N_NODES / 16;

    for (int t = gw; t < ntiles; t += nwarps) {
        const int node = t * 16 + m;
        const float* s1 = in1 + (size_t)node * W1IN;
        const float* s2 = (KDIM > W1IN) ? in2 + (size_t)node * (KDIM - W1IN) : nullptr;

        u64 acc[4][4];
#pragma unroll
        for (int d = 0; d < 4; d++)
#pragma unroll
            for (int g = 0; g < 4; g++) acc[d][g] = biasr[g];

#pragma unroll
        for (int c0 = 0; c0 < KDIM; c0 += 64) {
            __syncwarp();
#pragma unroll
            for (int i = 0; i < 8; i++) {
                int kk = c0 + half * 32 + i * 4;
                float4 v;
                if (KDIM == W1IN || kk < W1IN) v = *(const float4*)(s1 + kk);
                else                           v = *(const float4*)(s2 + (kk - W1IN));
                int kl = kk - c0;
                xs[(kl + 0) * 16 + m] = v.x;
                xs[(kl + 1) * 16 + m] = v.y;
                xs[(kl + 2) * 16 + m] = v.z;
                xs[(kl + 3) * 16 + m] = v.w;
            }
            __syncwarp();

#pragma unroll 4
            for (int k = 0; k < 64; k++) {
                float4 xv = *(const float4*)&xs[k * 16 + q * 4];
                const ulonglong2* wp = (const ulonglong2*)(ws + (c0 + k) * 64 + p * 8);
                ulonglong2 wa = wp[0];
                ulonglong2 wb = wp[1];
                u64 xp[4] = {pack2(xv.x), pack2(xv.y), pack2(xv.z), pack2(xv.w)};
#pragma unroll
                for (int d = 0; d < 4; d++) {
                    ffma2(acc[d][0], xp[d], wa.x);
                    ffma2(acc[d][1], xp[d], wa.y);
                    ffma2(acc[d][2], xp[d], wb.x);
                    ffma2(acc[d][3], xp[d], wb.y);
                }
            }
        }

#pragma unroll
        for (int d = 0; d < 4; d++) {
            int nn = t * 16 + q * 4 + d;
            float* dst = out + (size_t)nn * NOUT_TOTAL + yoff + p * 8;
#pragma unroll
            for (int g = 0; g < 2; g++) {
                float2 a = unpack2(acc[d][2 * g]);
                float2 c = unpack2(acc[d][2 * g + 1]);
                float4 v = make_float4(a.x, a.y, c.x, c.y);
                if (DO_SILU) {
                    v.x = silu(v.x); v.y = silu(v.y);
                    v.z = silu(v.z); v.w = silu(v.w);
                }
                if (DO_RES) {
                    float4 r = *(const float4*)(dst + g * 4);
                    v.x += r.x; v.y += r.y; v.z += r.z; v.w += r.w;
                }
                *(float4*)(dst + g * 4) = v;
            }
        }
    }
}

// ---------------------------------------------------------------------------
// Edge kernel: sorted edges; gather+silu -> tf32 mma MLP2 ->
// tile-local segmented reduction -> red4 per run.
// ---------------------------------------------------------------------------
#define SM_IDX  0
#define SM_B2S  128
#define SM_X2   192
#define SM_B2P  (192 + 128 * XSTR)
#define SM_EDGE_FLOATS (SM_B2P + 8 * 4 * 32 * 4)
#define SM_EDGE_BYTES  (SM_EDGE_FLOATS * 4)

__global__ void __launch_bounds__(256, 3)
edge_kernel2(const int* __restrict__ srow, const int* __restrict__ scol,
             const float* __restrict__ P,
             const float* __restrict__ W2, const float* __restrict__ b2)
{
    extern __shared__ float sm[];
    int*   idxs = (int*)sm;
    float* b2s  = sm + SM_B2S;
    float* X2   = sm + SM_X2;
    float* B2p  = sm + SM_B2P;

    const int tid  = threadIdx.x;
    const int warp = tid >> 5, lane = tid & 31;
    const int g    = lane >> 2, tig = lane & 3;

    for (int i = tid; i < 8 * 4 * 32; i += 256) {
        int s  = i >> 7;
        int gp = (i >> 5) & 3;
        int ln = i & 31;
        int gg = ln >> 2, tt = ln & 3;
        int k0 = s * 8;
        int nA = gp * 16 + (gg >> 1) * 4 + (gg & 1);
        int nB = nA + 2;
        float4 v;
        v.x = tf32f(W2[(k0 + tt)     * 64 + nA]);
        v.y = tf32f(W2[(k0 + tt + 4) * 64 + nA]);
        v.z = tf32f(W2[(k0 + tt)     * 64 + nB]);
        v.w = tf32f(W2[(k0 + tt + 4) * 64 + nB]);
        *(float4*)&B2p[i * 4] = v;
    }
    if (tid < 64) b2s[tid] = b2[tid];
    __syncthreads();

    const float* xlo = X2 + (warp * 16 + g) * XSTR + tig * 2;
    const float* xhi = xlo + 8 * XSTR;
    const int e_lo = warp * 16 + g;
    const int e_hi = e_lo + 8;
    const int qd = tid & 15;        // column quad 0..15 (reduction pass)
    const int sp = tid >> 4;        // edge strip 0..15 (8 edges each)

    for (int t = blockIdx.x; t < E_EDGES / ET; t += gridDim.x) {
        // ---- gather + silu -> X2 (frag-interleaved tf32) ----
        {
            int e = tid >> 1, half = tid & 1;
            int row  = srow[t * ET + e];
            int coln = scol[t * ET + e];
            if (half == 0) idxs[e] = row;
            const float4* pa = (const float4*)(P + (size_t)row  * HID + half * 32);
            const float4* pb = (const float4*)(P + (size_t)coln * HID + 64 + half * 32);
            float va[32];
#pragma unroll
            for (int i = 0; i < 8; i++) {
                float4 x = pa[i];
                float4 y = pb[i];
                va[i * 4 + 0] = tf32f(silu(x.x + y.x));
                va[i * 4 + 1] = tf32f(silu(x.y + y.y));
                va[i * 4 + 2] = tf32f(silu(x.z + y.z));
                va[i * 4 + 3] = tf32f(silu(x.w + y.w));
            }
            float* xr = X2 + e * XSTR;
#pragma unroll
            for (int b = 0; b < 4; b++)
#pragma unroll
                for (int j = 0; j < 4; j++) {
                    float2 v = make_float2(va[(b * 2) * 4 + j], va[(b * 2 + 1) * 4 + j]);
                    *(float2*)&xr[(half * 4 + b) * 8 + j * 2] = v;
                }
        }
        __syncthreads();

        // ---- MLP2 MMA ----
        float acc[8][4];
#pragma unroll
        for (int a = 0; a < 8; a++)
#pragma unroll
            for (int c = 0; c < 4; c++) acc[a][c] = 0.f;

#pragma unroll
        for (int s = 0; s < 8; s++) {
            float2 alo = *(const float2*)(xlo + s * 8);
            float2 ahi = *(const float2*)(xhi + s * 8);
            u32 a0 = __float_as_uint(alo.x), a1 = __float_as_uint(ahi.x);
            u32 a2 = __float_as_uint(alo.y), a3 = __float_as_uint(ahi.y);
#pragma unroll
            for (int gp = 0; gp < 4; gp++) {
                float4 bv = *(const float4*)&B2p[((s * 4 + gp) * 32 + lane) * 4];
                mma_tf32(acc[gp * 2 + 0], a0, a1, a2, a3,
                         __float_as_uint(bv.x), __float_as_uint(bv.y));
                mma_tf32(acc[gp * 2 + 1], a0, a1, a2, a3,
                         __float_as_uint(bv.z), __float_as_uint(bv.w));
            }
        }
        __syncthreads();   // all MMA reads of X2 done; safe to overwrite

        // ---- write silu(D2 + b2) back into X2 as R[e][0..63] (stride XSTR) ----
        {
            float* rlo = X2 + e_lo * XSTR;
            float* rhi = X2 + e_hi * XSTR;
#pragma unroll
            for (int gp = 0; gp < 4; gp++) {
                int c0 = gp * 16 + tig * 4;
                *(float2*)&rlo[c0]     = make_float2(silu(acc[gp*2][0]   + b2s[c0]),
                                                     silu(acc[gp*2][1]   + b2s[c0+1]));
                *(float2*)&rlo[c0 + 2] = make_float2(silu(acc[gp*2+1][0] + b2s[c0+2]),
                                                     silu(acc[gp*2+1][1] + b2s[c0+3]));
                *(float2*)&rhi[c0]     = make_float2(silu(acc[gp*2][2]   + b2s[c0]),
                                                     silu(acc[gp*2][3]   + b2s[c0+1]));
                *(float2*)&rhi[c0 + 2] = make_float2(silu(acc[gp*2+1][2] + b2s[c0+2]),
                                                     silu(acc[gp*2+1][3] + b2s[c0+3]));
            }
        }
        __syncthreads();

        // ---- segmented reduction: thread (qd, sp) walks 8 edges for 4 cols ----
        {
            int e0 = sp * 8;
            int cur = idxs[e0];
            const float* r = X2 + e0 * XSTR + qd * 4;
            float2 a01 = *(const float2*)(r);
            float2 a23 = *(const float2*)(r + 2);
            float s0 = a01.x, s1 = a01.y, s2 = a23.x, s3 = a23.y;
#pragma unroll
            for (int j = 1; j < 8; j++) {
                int rw = idxs[e0 + j];
                const float* rr = X2 + (e0 + j) * XSTR + qd * 4;
                float2 b01 = *(const float2*)(rr);
                float2 b23 = *(const float2*)(rr + 2);
                if (rw != cur) {
                    red4(g_agg + (size_t)cur * EH + qd * 4, s0, s1, s2, s3);
                    cur = rw;
                    s0 = b01.x; s1 = b01.y; s2 = b23.x; s3 = b23.y;
                } else {
                    s0 += b01.x; s1 += b01.y; s2 += b23.x; s3 += b23.y;
                }
            }
            red4(g_agg + (size_t)cur * EH + qd * 4, s0, s1, s2, s3);
        }
        __syncthreads();
    }
}

// ---------------------------------------------------------------------------
extern "C" void kernel_launch(void* const* d_in, const int* in_sizes, int n_in,
                              void* d_out, int out_size)
{
    const float* h_in  = (const float*)d_in[0];
    const int*   edges = (const int*)d_in[1];
    const float* W_in  = (const float*)d_in[2];
    const float* b_in  = (const float*)d_in[3];
    const float* eW1   = (const float*)d_in[4];
    const float* eb1   = (const float*)d_in[5];
    const float* eW2   = (const float*)d_in[6];
    const float* eb2   = (const float*)d_in[7];
    const float* nW1   = (const float*)d_in[8];
    const float* nb1   = (const float*)d_in[9];
    const float* nW2   = (const float*)d_in[10];
    const float* nb2   = (const float*)d_in[11];
    const float* W_out = (const float*)d_in[12];
    const float* b_out = (const float*)d_in[13];

    float* ph;   cudaGetSymbolAddress((void**)&ph,   g_h);
    float* pag;  cudaGetSymbolAddress((void**)&pag,  g_agg);
    float* pz;   cudaGetSymbolAddress((void**)&pz,   g_z);
    float* pwc;  cudaGetSymbolAddress((void**)&pwc,  g_wcat);
    float* pbc;  cudaGetSymbolAddress((void**)&pbc,  g_bcat);
    int* psrow;  cudaGetSymbolAddress((void**)&psrow, g_srow);
    int* pscol;  cudaGetSymbolAddress((void**)&pscol, g_scol);

    auto smem_g3 = [](int kdim) { return (kdim * 64 + 64 + 8 * 64 * 16) * 4; };
    const int sm_ei  = smem_g3(64);
    const int sm_p   = smem_g3(128);
    const int sm_m128 = (64 + 128 * XSTR + 16 * 4 * 32 * 4) * 4;
    const int sm_m192 = (64 + 128 * XSTR + 24 * 4 * 32 * 4) * 4;

    cudaFuncSetAttribute(edge_kernel2, cudaFuncAttributeMaxDynamicSharedMemorySize, SM_EDGE_BYTES);
    cudaFuncSetAttribute(node_mma<128, 128, false>,
                         cudaFuncAttributeMaxDynamicSharedMemorySize, sm_m128);
    cudaFuncSetAttribute(node_mma<192, 128, true>,
                         cudaFuncAttributeMaxDynamicSharedMemorySize, sm_m192);
    cudaFuncSetAttribute(node_gemm3<64, 64, 128, false, false>,
                         cudaFuncAttributeMaxDynamicSharedMemorySize, sm_ei);
    cudaFuncSetAttribute(node_gemm3<128, 128, 128, false, true>,
                         cudaFuncAttributeMaxDynamicSharedMemorySize, sm_p);
    cudaFuncSetAttribute(node_gemm3<128, 128, 64, false, false>,
                         cudaFuncAttributeMaxDynamicSharedMemorySize, sm_p);

    const int EB = (E_EDGES + 255) / 256;

    k_zero_deg<<<SCAN_BLOCKS, 256>>>();
    k_hist<<<EB, 256>>>(edges);
    k_scan1<<<SCAN_BLOCKS, 256>>>();
    k_scan2<<<1, 256>>>();
    k_scan3<<<SCAN_BLOCKS, 256>>>();
    k_sort_scatter<<<EB, 256>>>(edges);

    node_gemm3<64, 64, 128, false, false><<<dim3(148, 2), 256, sm_ei>>>(
        h_in, nullptr, W_in, b_in, ph);

    for (int l = 0; l < L_LAYERS; l++) {
        prep_layer<<<(N_NODES * EH / 4 + 255) / 256, 256>>>(
            eW1 + l * 2 * HID * EH, eb1 + l * EH);
        node_mma<128, 128, false><<<dim3(148, 2), 256, sm_m128>>>(
            ph, nullptr, pwc, pbc, pz);
        edge_kernel2<<<444, 256, SM_EDGE_BYTES>>>(
            psrow, pscol, pz, eW2 + l * EH * EH, eb2 + l * EH);
        node_mma<192, 128, true><<<dim3(148, 2), 256, sm_m192>>>(
            ph, pag, nW1 + l * (HID + EH) * HID, nb1 + l * HID, pz);
        node_gemm3<128, 128, 128, false, true><<<dim3(148, 2), 256, sm_p>>>(
            pz, nullptr, nW2 + l * HID * HID, nb2 + l * HID, ph);
    }

    node_gemm3<128, 128, 64, false, false><<<dim3(148, 1), 256, sm_p>>>(
        ph, nullptr, W_out, b_out, (float*)d_out);
}